// round 6
// baseline (speedup 1.0000x reference)
#include <cuda_runtime.h>
#include <cuda_bf16.h>

// ---------------------------------------------------------------------------
// SparseMemory read:  q = X@Wq^T+bq ; k,v = M@W^T+b ; S = qk^T/32 ;
// top-32 per row -> softmax -> ctx = sum p_i * V[idx_i] ; out = ctx@Wo^T+bo
//
// Shapes: B=4, T=2048, S=4096, D=1024, TOPK=32. fp32 I/O.
//
// NUMERICS (evidence rounds 1/3): reference is accurate fp32 (TF32 emulation
// made error 15x WORSE); rel_err is dominated by top-32 selection swaps at the
// rank boundary (1 swap ~ 2.2e-3 global; threshold needs ZERO swaps).
// Strategy: fp32 GEMMs for values; top-48 candidates by fp32 score; exact fp64
// rescore of candidates from the same fp32 q,k; fp64 ranking (tie -> lower
// index, matching lax.top_k). Removes all my-side score noise from selection.
// ---------------------------------------------------------------------------

#define BATCH   4
#define TQ      2048
#define SS      4096
#define DD      1024
#define TOPK    32
#define NCAND   48          // candidate pool (top-48 by fp32 score)

#define MQ      (BATCH*TQ)      // 8192  rows for Q / ctx / out
#define MKV     (BATCH*SS)      // 16384 rows for K / V

// Scratch (device globals: allocation-free per harness rules)
__device__ float g_Q  [8192u  * 1024u];   // 32 MB
__device__ float g_K  [16384u * 1024u];   // 64 MB
__device__ float g_V  [16384u * 1024u];   // 64 MB
__device__ float g_S  [33554432u];        // 4*2048*4096 = 134 MB
__device__ float g_CTX[8192u  * 1024u];   // 32 MB

// ---------------------------------------------------------------------------
// Tiled SGEMM, NT layout: C[M,N] = alpha * A(MxKd) * B(NxKd)^T + bias[N]
// Pure fp32 FFMA, strictly ascending-k single-chain accumulation.
// Double-buffered smem. 128x128 tile, BK=16, 256 threads, 8x8 per thread.
// ---------------------------------------------------------------------------
#define BM 128
#define BN 128
#define BK 16
#define TM 8
#define TN 8

__global__ __launch_bounds__(256, 2)
void gemm_nt(const float* __restrict__ A, const float* __restrict__ B,
             float* __restrict__ C, const float* __restrict__ bias,
             int M, int N, int Kd, float alpha,
             long long strideA, long long strideB, long long strideC)
{
    __shared__ float As[2][BK][BM];
    __shared__ float Bs[2][BK][BN];

    const int bx = blockIdx.x;   // N tile
    const int by = blockIdx.y;   // M tile
    const int bz = blockIdx.z;   // batch

    A += bz * strideA + (long long)by * BM * Kd;
    B += bz * strideB + (long long)bx * BN * Kd;
    C += bz * strideC;

    const int tid  = threadIdx.x;
    const int tx   = tid & 15;         // 0..15 -> N
    const int ty   = tid >> 4;         // 0..15 -> M
    const int lrow = tid >> 2;         // 0..63
    const int lcol = (tid & 3) * 4;    // 0,4,8,12

    float acc[TM][TN];
    #pragma unroll
    for (int i = 0; i < TM; ++i)
        #pragma unroll
        for (int j = 0; j < TN; ++j) acc[i][j] = 0.f;

    float4 pa[2], pb[2];

    // prefetch k-tile 0
    #pragma unroll
    for (int r = 0; r < 2; ++r) {
        pa[r] = *(const float4*)(A + (long long)(lrow + r * 64) * Kd + lcol);
        pb[r] = *(const float4*)(B + (long long)(lrow + r * 64) * Kd + lcol);
    }
    #pragma unroll
    for (int r = 0; r < 2; ++r) {
        int row = lrow + r * 64;
        As[0][lcol + 0][row] = pa[r].x;
        As[0][lcol + 1][row] = pa[r].y;
        As[0][lcol + 2][row] = pa[r].z;
        As[0][lcol + 3][row] = pa[r].w;
        Bs[0][lcol + 0][row] = pb[r].x;
        Bs[0][lcol + 1][row] = pb[r].y;
        Bs[0][lcol + 2][row] = pb[r].z;
        Bs[0][lcol + 3][row] = pb[r].w;
    }
    __syncthreads();

    int buf = 0;
    for (int k0 = 0; k0 < Kd; k0 += BK) {
        const int k1 = k0 + BK;
        const bool more = (k1 < Kd);

        if (more) {
            #pragma unroll
            for (int r = 0; r < 2; ++r) {
                pa[r] = *(const float4*)(A + (long long)(lrow + r * 64) * Kd + k1 + lcol);
                pb[r] = *(const float4*)(B + (long long)(lrow + r * 64) * Kd + k1 + lcol);
            }
        }

        #pragma unroll
        for (int kk = 0; kk < BK; ++kk) {
            float a[TM], b[TN];
            *(float4*)&a[0] = *(const float4*)&As[buf][kk][ty * TM];
            *(float4*)&a[4] = *(const float4*)&As[buf][kk][ty * TM + 4];
            *(float4*)&b[0] = *(const float4*)&Bs[buf][kk][tx * TN];
            *(float4*)&b[4] = *(const float4*)&Bs[buf][kk][tx * TN + 4];
            #pragma unroll
            for (int i = 0; i < TM; ++i)
                #pragma unroll
                for (int j = 0; j < TN; ++j)
                    acc[i][j] = fmaf(a[i], b[j], acc[i][j]);
        }

        if (more) {
            const int nb = buf ^ 1;
            #pragma unroll
            for (int r = 0; r < 2; ++r) {
                int row = lrow + r * 64;
                As[nb][lcol + 0][row] = pa[r].x;
                As[nb][lcol + 1][row] = pa[r].y;
                As[nb][lcol + 2][row] = pa[r].z;
                As[nb][lcol + 3][row] = pa[r].w;
                Bs[nb][lcol + 0][row] = pb[r].x;
                Bs[nb][lcol + 1][row] = pb[r].y;
                Bs[nb][lcol + 2][row] = pb[r].z;
                Bs[nb][lcol + 3][row] = pb[r].w;
            }
            __syncthreads();
            buf = nb;
        }
    }

    #pragma unroll
    for (int i = 0; i < TM; ++i) {
        int row = by * BM + ty * TM + i;
        float* crow = C + (long long)row * N;
        #pragma unroll
        for (int j4 = 0; j4 < TN; j4 += 4) {
            int col = bx * BN + tx * TN + j4;
            float4 o;
            o.x = acc[i][j4 + 0] * alpha;
            o.y = acc[i][j4 + 1] * alpha;
            o.z = acc[i][j4 + 2] * alpha;
            o.w = acc[i][j4 + 3] * alpha;
            if (bias) {
                float4 bb = *(const float4*)(bias + col);
                o.x += bb.x; o.y += bb.y; o.z += bb.z; o.w += bb.w;
            }
            *(float4*)(crow + col) = o;
        }
    }
}

// ---------------------------------------------------------------------------
// Per-query-row: top-48 candidates by fp32 score -> exact fp64 rescore of the
// candidates from the same fp32 q,k -> fp64 top-32 (single-thread selection
// sort; tie -> lower index) -> fp32 softmax -> ctx = sum p_i V[idx_i].
// One CTA (256 thr) per query row.
// ---------------------------------------------------------------------------
#define NEG_HUGE (-3.402823466e38f)
#define NEG_HUGE_D (-1e300)
#define SCALE_D (0.03125)   // 1/sqrt(1024) exact

__global__ __launch_bounds__(256)
void topk_softmax_av(const float* __restrict__ scores,
                     const float* __restrict__ Q,
                     const float* __restrict__ Km,
                     const float* __restrict__ V,
                     float* __restrict__ ctx)
{
    const int r = blockIdx.x;            // 0..8191 (query row)
    const int b = r >> 11;               // batch
    const int tid  = threadIdx.x;
    const int lane = tid & 31;
    const int wid  = tid >> 5;

    __shared__ float  sc[SS];            // 16 KB fp32 scores
    __shared__ float  qrow[DD];          // 4 KB  q row
    __shared__ float  rv[256];
    __shared__ int    ri[256];
    __shared__ int    cidx[NCAND];       // candidate mem indices
    __shared__ double cval[NCAND];       // exact raw scores of candidates
    __shared__ float  selv[TOPK];        // selected scaled fp32 scores
    __shared__ int    seli[TOPK];        // selected mem indices
    __shared__ float  prob[TOPK];

    const float* srow = scores + (long long)r * SS;
    for (int j = tid; j < SS; j += 256) sc[j] = srow[j];
    const float* qsrc = Q + (long long)r * DD;
    for (int j = tid; j < DD; j += 256) qrow[j] = qsrc[j];
    __syncthreads();

    // ---- Phase 1: top-48 candidates by fp32 score (iterated block argmax) ----
    float lmax = NEG_HUGE;
    int   lidx = tid * 16;
    {
        const int base = tid * 16;
        #pragma unroll
        for (int j = 0; j < 16; ++j) {
            float v = sc[base + j];
            if (v > lmax) { lmax = v; lidx = base + j; }
        }
    }

    for (int it = 0; it < NCAND; ++it) {
        rv[tid] = lmax;
        ri[tid] = lidx;
        __syncthreads();
        #pragma unroll
        for (int s = 128; s > 0; s >>= 1) {
            if (tid < s) {
                float ov = rv[tid + s]; int oi = ri[tid + s];
                if (ov > rv[tid] || (ov == rv[tid] && oi < ri[tid])) {
                    rv[tid] = ov; ri[tid] = oi;
                }
            }
            __syncthreads();
        }
        const int gi = ri[0];
        if (tid == 0) cidx[it] = gi;
        if ((gi >> 4) == tid) {
            sc[gi] = NEG_HUGE;
            lmax = NEG_HUGE;
            const int base = tid * 16;
            lidx = base;
            #pragma unroll
            for (int j = 0; j < 16; ++j) {
                float v = sc[base + j];
                if (v > lmax) { lmax = v; lidx = base + j; }
            }
        }
        __syncthreads();
    }

    // ---- Phase 2: exact fp64 rescore of 48 candidates (warp w: cands 6w..6w+5)
    const float* Kb = Km + (long long)b * SS * DD;
    for (int t = 0; t < 6; ++t) {
        const int c  = wid * 6 + t;
        const int mi = cidx[c];
        const float* krow = Kb + (long long)mi * DD;
        double s = 0.0;
        #pragma unroll 8
        for (int i = 0; i < 32; ++i) {
            int d = lane + 32 * i;       // coalesced across lanes
            s += (double)qrow[d] * (double)krow[d];
        }
        #pragma unroll
        for (int off = 16; off > 0; off >>= 1)
            s += __shfl_xor_sync(0xffffffffu, s, off);
        if (lane == 0) cval[c] = s;
    }
    __syncthreads();

    // ---- Phase 3: fp64 top-32 of 48, single-thread selection sort ----
    // (tie -> lower mem index, matching lax.top_k). CTAs are the parallel axis;
    // 48*32 scalar compares per row is negligible.
    if (tid == 0) {
        bool used[NCAND];
        #pragma unroll
        for (int c = 0; c < NCAND; ++c) used[c] = false;
        for (int round = 0; round < TOPK; ++round) {
            double bv = NEG_HUGE_D; int bi = 0x7fffffff; int bc = 0;
            for (int c = 0; c < NCAND; ++c) {
                if (used[c]) continue;
                double v = cval[c]; int ix = cidx[c];
                if (v > bv || (v == bv && ix < bi)) { bv = v; bi = ix; bc = c; }
            }
            used[bc] = true;
            selv[round] = (float)(bv * SCALE_D);   // exact *1/32, round to fp32
            seli[round] = bi;
        }
    }
    __syncthreads();

    // ---- Phase 4: softmax over selected 32 (selv[0] is the max) ----
    if (tid < 32) {
        float e = expf(selv[tid] - selv[0]);
        float s = e;
        #pragma unroll
        for (int off = 16; off > 0; off >>= 1)
            s += __shfl_xor_sync(0xffffffffu, s, off);
        prob[tid] = e / s;
    }
    __syncthreads();

    // ---- Phase 5: ctx[r,:] = sum_i prob[i] * V[b, seli[i], :] ----
    const float* Vb = V + (long long)b * SS * DD;
    const int d = tid * 4;
    float4 accv = make_float4(0.f, 0.f, 0.f, 0.f);
    #pragma unroll 4
    for (int i = 0; i < TOPK; ++i) {
        const float p = prob[i];
        float4 v = *(const float4*)(Vb + (long long)seli[i] * DD + d);
        accv.x = fmaf(p, v.x, accv.x);
        accv.y = fmaf(p, v.y, accv.y);
        accv.z = fmaf(p, v.z, accv.z);
        accv.w = fmaf(p, v.w, accv.w);
    }
    *(float4*)(ctx + (long long)r * DD + d) = accv;
}

// ---------------------------------------------------------------------------
// Launch
// ---------------------------------------------------------------------------
extern "C" void kernel_launch(void* const* d_in, const int* in_sizes, int n_in,
                              void* d_out, int out_size)
{
    const float* query = (const float*)d_in[0];   // (4,2048,1024)
    const float* mem   = (const float*)d_in[1];   // (4,4096,1024)
    // d_in[2] = top_k scalar (compile-time 32)
    const float* Wq = (const float*)d_in[3];
    const float* bq = (const float*)d_in[4];
    const float* Wk = (const float*)d_in[5];
    const float* bk = (const float*)d_in[6];
    const float* Wv = (const float*)d_in[7];
    const float* bv = (const float*)d_in[8];
    const float* Wo = (const float*)d_in[9];
    const float* bo = (const float*)d_in[10];
    float* out = (float*)d_out;

    float *Q, *K, *V, *S, *CTX;
    cudaGetSymbolAddress((void**)&Q,   g_Q);
    cudaGetSymbolAddress((void**)&K,   g_K);
    cudaGetSymbolAddress((void**)&V,   g_V);
    cudaGetSymbolAddress((void**)&S,   g_S);
    cudaGetSymbolAddress((void**)&CTX, g_CTX);

    const float inv_sqrt_d = 1.0f / 32.0f;   // 1/sqrt(1024)

    // Projections (fp32)
    gemm_nt<<<dim3(DD / BN, MQ  / BM, 1), 256>>>(query, Wq, Q, bq, MQ,  DD, DD, 1.f, 0, 0, 0);
    gemm_nt<<<dim3(DD / BN, MKV / BM, 1), 256>>>(mem,   Wk, K, bk, MKV, DD, DD, 1.f, 0, 0, 0);
    gemm_nt<<<dim3(DD / BN, MKV / BM, 1), 256>>>(mem,   Wv, V, bv, MKV, DD, DD, 1.f, 0, 0, 0);

    // Scores (fp32, scaled) — used for candidate finding only
    gemm_nt<<<dim3(SS / BN, TQ / BM, BATCH), 256>>>(
        Q, K, S, nullptr, TQ, SS, DD, inv_sqrt_d,
        (long long)TQ * DD, (long long)SS * DD, (long long)TQ * SS);

    // Top-48 candidates -> exact fp64 rescore -> top-32 -> softmax -> sparse AV
    topk_softmax_av<<<MQ, 256>>>(S, Q, K, V, CTX);

    // Output projection (fp32)
    gemm_nt<<<dim3(DD / BN, MQ / BM, 1), 256>>>(CTX, Wo, out, bo, MQ, DD, DD, 1.f, 0, 0, 0);
}

// round 7
// speedup vs baseline: 1.3701x; 1.3701x over previous
#include <cuda_runtime.h>
#include <cuda_bf16.h>
#include <cstdint>

// ---------------------------------------------------------------------------
// SparseMemory read. Shapes: B=4, T=2048, S=4096, D=1024, TOPK=32. fp32 I/O.
//
// NUMERICS CONTRACT (validated round 6, rel_err 9.2e-7):
//  - Q/K/V/O projections: fp32 FFMA gemm_nt, accumulation chain FROZEN
//    (the fp64 rescore treats these q,k as ground truth).
//  - Scores GEMM: candidate-nomination only -> bf16 tensor cores are safe
//    (bf16 noise ~1.6e-3 << rank32->rank48 margin ~0.07).
//  - Selection: top-48 by approx score, exact fp64 rescore, fp64 top-32
//    (tie -> lower index). PRESERVED EXACTLY.
// ---------------------------------------------------------------------------

#define BATCH   4
#define TQ      2048
#define SS      4096
#define DD      1024
#define TOPK    32
#define NCAND   48

#define MQ      (BATCH*TQ)      // 8192
#define MKV     (BATCH*SS)      // 16384

// Scratch (device globals: allocation-free per harness rules)
__device__ float g_Q  [8192u  * 1024u];   // 32 MB
__device__ float g_K  [16384u * 1024u];   // 64 MB
__device__ float g_V  [16384u * 1024u];   // 64 MB
__device__ float g_S  [33554432u];        // 134 MB
__device__ float g_CTX[8192u  * 1024u];   // 32 MB
__device__ __nv_bfloat16 g_Qh[8192u  * 1024u];   // 16 MB
__device__ __nv_bfloat16 g_Kh[16384u * 1024u];   // 32 MB

// ---------------------------------------------------------------------------
// fp32 tiled SGEMM (FROZEN — do not alter accumulation semantics)
// NT: C[M,N] = alpha * A(MxKd) * B(NxKd)^T + bias[N]
// ---------------------------------------------------------------------------
#define BM 128
#define BN 128
#define BK 16
#define TM 8
#define TN 8

__global__ __launch_bounds__(256, 2)
void gemm_nt(const float* __restrict__ A, const float* __restrict__ B,
             float* __restrict__ C, const float* __restrict__ bias,
             int M, int N, int Kd, float alpha,
             long long strideA, long long strideB, long long strideC)
{
    __shared__ float As[2][BK][BM];
    __shared__ float Bs[2][BK][BN];

    const int bx = blockIdx.x;
    const int by = blockIdx.y;
    const int bz = blockIdx.z;

    A += bz * strideA + (long long)by * BM * Kd;
    B += bz * strideB + (long long)bx * BN * Kd;
    C += bz * strideC;

    const int tid  = threadIdx.x;
    const int tx   = tid & 15;
    const int ty   = tid >> 4;
    const int lrow = tid >> 2;
    const int lcol = (tid & 3) * 4;

    float acc[TM][TN];
    #pragma unroll
    for (int i = 0; i < TM; ++i)
        #pragma unroll
        for (int j = 0; j < TN; ++j) acc[i][j] = 0.f;

    float4 pa[2], pb[2];

    #pragma unroll
    for (int r = 0; r < 2; ++r) {
        pa[r] = *(const float4*)(A + (long long)(lrow + r * 64) * Kd + lcol);
        pb[r] = *(const float4*)(B + (long long)(lrow + r * 64) * Kd + lcol);
    }
    #pragma unroll
    for (int r = 0; r < 2; ++r) {
        int row = lrow + r * 64;
        As[0][lcol + 0][row] = pa[r].x;
        As[0][lcol + 1][row] = pa[r].y;
        As[0][lcol + 2][row] = pa[r].z;
        As[0][lcol + 3][row] = pa[r].w;
        Bs[0][lcol + 0][row] = pb[r].x;
        Bs[0][lcol + 1][row] = pb[r].y;
        Bs[0][lcol + 2][row] = pb[r].z;
        Bs[0][lcol + 3][row] = pb[r].w;
    }
    __syncthreads();

    int buf = 0;
    for (int k0 = 0; k0 < Kd; k0 += BK) {
        const int k1 = k0 + BK;
        const bool more = (k1 < Kd);

        if (more) {
            #pragma unroll
            for (int r = 0; r < 2; ++r) {
                pa[r] = *(const float4*)(A + (long long)(lrow + r * 64) * Kd + k1 + lcol);
                pb[r] = *(const float4*)(B + (long long)(lrow + r * 64) * Kd + k1 + lcol);
            }
        }

        #pragma unroll
        for (int kk = 0; kk < BK; ++kk) {
            float a[TM], b[TN];
            *(float4*)&a[0] = *(const float4*)&As[buf][kk][ty * TM];
            *(float4*)&a[4] = *(const float4*)&As[buf][kk][ty * TM + 4];
            *(float4*)&b[0] = *(const float4*)&Bs[buf][kk][tx * TN];
            *(float4*)&b[4] = *(const float4*)&Bs[buf][kk][tx * TN + 4];
            #pragma unroll
            for (int i = 0; i < TM; ++i)
                #pragma unroll
                for (int j = 0; j < TN; ++j)
                    acc[i][j] = fmaf(a[i], b[j], acc[i][j]);
        }

        if (more) {
            const int nb = buf ^ 1;
            #pragma unroll
            for (int r = 0; r < 2; ++r) {
                int row = lrow + r * 64;
                As[nb][lcol + 0][row] = pa[r].x;
                As[nb][lcol + 1][row] = pa[r].y;
                As[nb][lcol + 2][row] = pa[r].z;
                As[nb][lcol + 3][row] = pa[r].w;
                Bs[nb][lcol + 0][row] = pb[r].x;
                Bs[nb][lcol + 1][row] = pb[r].y;
                Bs[nb][lcol + 2][row] = pb[r].z;
                Bs[nb][lcol + 3][row] = pb[r].w;
            }
            __syncthreads();
            buf = nb;
        }
    }

    #pragma unroll
    for (int i = 0; i < TM; ++i) {
        int row = by * BM + ty * TM + i;
        float* crow = C + (long long)row * N;
        #pragma unroll
        for (int j4 = 0; j4 < TN; j4 += 4) {
            int col = bx * BN + tx * TN + j4;
            float4 o;
            o.x = acc[i][j4 + 0] * alpha;
            o.y = acc[i][j4 + 1] * alpha;
            o.z = acc[i][j4 + 2] * alpha;
            o.w = acc[i][j4 + 3] * alpha;
            if (bias) {
                float4 bb = *(const float4*)(bias + col);
                o.x += bb.x; o.y += bb.y; o.z += bb.z; o.w += bb.w;
            }
            *(float4*)(crow + col) = o;
        }
    }
}

// ---------------------------------------------------------------------------
// fp32 -> bf16 conversion (grid-stride over float4)
// ---------------------------------------------------------------------------
__global__ __launch_bounds__(256)
void f32_to_bf16_kernel(const float* __restrict__ in, __nv_bfloat16* __restrict__ out, int n4)
{
    int i = blockIdx.x * blockDim.x + threadIdx.x;
    if (i < n4) {
        float4 v = ((const float4*)in)[i];
        __nv_bfloat162 lo = __floats2bfloat162_rn(v.x, v.y);
        __nv_bfloat162 hi = __floats2bfloat162_rn(v.z, v.w);
        ((__nv_bfloat162*)out)[2 * i + 0] = lo;
        ((__nv_bfloat162*)out)[2 * i + 1] = hi;
    }
}

// ---------------------------------------------------------------------------
// bf16 tensor-core scores GEMM: S[b] = Qh[b](2048x1024) * Kh[b](4096x1024)^T /32
// CTA 128x128, BK=32, 8 warps (4Mx2N), warp tile 32x64, mma.m16n8k16.
// Swizzled smem + ldmatrix, double-buffered.
// ---------------------------------------------------------------------------
__device__ __forceinline__ uint32_t smem_u32p(const void* p) {
    return (uint32_t)__cvta_generic_to_shared(p);
}

__device__ __forceinline__ void ldsm_x4(uint32_t& r0, uint32_t& r1, uint32_t& r2, uint32_t& r3,
                                        uint32_t addr)
{
    asm volatile("ldmatrix.sync.aligned.m8n8.x4.shared.b16 {%0,%1,%2,%3}, [%4];"
                 : "=r"(r0), "=r"(r1), "=r"(r2), "=r"(r3) : "r"(addr));
}

__device__ __forceinline__ void mma_bf16(float* d, const uint32_t* a, uint32_t b0, uint32_t b1)
{
    asm volatile("mma.sync.aligned.m16n8k16.row.col.f32.bf16.bf16.f32 "
                 "{%0,%1,%2,%3}, {%4,%5,%6,%7}, {%8,%9}, {%0,%1,%2,%3};"
                 : "+f"(d[0]), "+f"(d[1]), "+f"(d[2]), "+f"(d[3])
                 : "r"(a[0]), "r"(a[1]), "r"(a[2]), "r"(a[3]), "r"(b0), "r"(b1));
}

// smem tile: 128 rows x 32 bf16 (64B/row = 4x16B chunks), swizzled
__device__ __forceinline__ int sw_off(int r, int c) {
    int phys = ((c ^ r) & 3) ^ ((r >> 2) & 1);
    return r * 64 + phys * 16;   // byte offset
}

__global__ __launch_bounds__(256)
void gemm_nt_bf16_scores(const __nv_bfloat16* __restrict__ A,
                         const __nv_bfloat16* __restrict__ Bm,
                         float* __restrict__ C, float alpha)
{
    __shared__ __align__(16) char As[2][128 * 64];
    __shared__ __align__(16) char Bs[2][128 * 64];

    const int bx = blockIdx.x;   // N tile (0..31)
    const int by = blockIdx.y;   // M tile (0..15)
    const int bz = blockIdx.z;   // batch

    const __nv_bfloat16* Ab = A  + (long long)bz * TQ * DD + (long long)by * 128 * DD;
    const __nv_bfloat16* Bb = Bm + (long long)bz * SS * DD + (long long)bx * 128 * DD;
    float* Cb = C + (long long)bz * TQ * SS;

    const int tid  = threadIdx.x;
    const int lane = tid & 31;
    const int wid  = tid >> 5;
    const int wm   = (wid & 3) * 32;
    const int wn   = (wid >> 2) * 64;

    // load indices: chunk ids tid and tid+256; r = id>>2, c = id&3
    const int r0 = tid >> 2,        c0 = tid & 3;
    const int r1 = (tid + 256) >> 2, c1 = (tid + 256) & 3;

    float acc[2][8][4];
    #pragma unroll
    for (int i = 0; i < 2; ++i)
        #pragma unroll
        for (int j = 0; j < 8; ++j)
            #pragma unroll
            for (int k = 0; k < 4; ++k) acc[i][j][k] = 0.f;

    uint4 pa0, pa1, pb0, pb1;

    // prefetch k-tile 0
    pa0 = *(const uint4*)(Ab + (long long)r0 * DD + c0 * 8);
    pa1 = *(const uint4*)(Ab + (long long)r1 * DD + c1 * 8);
    pb0 = *(const uint4*)(Bb + (long long)r0 * DD + c0 * 8);
    pb1 = *(const uint4*)(Bb + (long long)r1 * DD + c1 * 8);
    *(uint4*)(As[0] + sw_off(r0, c0)) = pa0;
    *(uint4*)(As[0] + sw_off(r1, c1)) = pa1;
    *(uint4*)(Bs[0] + sw_off(r0, c0)) = pb0;
    *(uint4*)(Bs[0] + sw_off(r1, c1)) = pb1;
    __syncthreads();

    int buf = 0;
    for (int k0 = 0; k0 < DD; k0 += 32) {
        const int k1 = k0 + 32;
        const bool more = (k1 < DD);

        if (more) {
            pa0 = *(const uint4*)(Ab + (long long)r0 * DD + k1 + c0 * 8);
            pa1 = *(const uint4*)(Ab + (long long)r1 * DD + k1 + c1 * 8);
            pb0 = *(const uint4*)(Bb + (long long)r0 * DD + k1 + c0 * 8);
            pb1 = *(const uint4*)(Bb + (long long)r1 * DD + k1 + c1 * 8);
        }

        const uint32_t aBase = smem_u32p(As[buf]);
        const uint32_t bBase = smem_u32p(Bs[buf]);

        #pragma unroll
        for (int tk = 0; tk < 2; ++tk) {
            // A fragments: 2 m16 tiles
            uint32_t afrag[2][4];
            #pragma unroll
            for (int tm = 0; tm < 2; ++tm) {
                int r = wm + tm * 16 + (lane & 7) + ((lane >> 3) & 1) * 8;
                int c = tk * 2 + (lane >> 4);
                ldsm_x4(afrag[tm][0], afrag[tm][1], afrag[tm][2], afrag[tm][3],
                        aBase + sw_off(r, c));
            }
            // B fragments: 4 groups of n16 (2 n8 tiles each)
            #pragma unroll
            for (int tn = 0; tn < 4; ++tn) {
                uint32_t bfrag[4];
                int r = wn + tn * 16 + (lane & 7) + ((lane >> 4) & 1) * 8;
                int c = tk * 2 + ((lane >> 3) & 1);
                ldsm_x4(bfrag[0], bfrag[1], bfrag[2], bfrag[3], bBase + sw_off(r, c));
                #pragma unroll
                for (int tm = 0; tm < 2; ++tm) {
                    mma_bf16(acc[tm][tn * 2 + 0], afrag[tm], bfrag[0], bfrag[1]);
                    mma_bf16(acc[tm][tn * 2 + 1], afrag[tm], bfrag[2], bfrag[3]);
                }
            }
        }

        if (more) {
            const int nb = buf ^ 1;
            *(uint4*)(As[nb] + sw_off(r0, c0)) = pa0;
            *(uint4*)(As[nb] + sw_off(r1, c1)) = pa1;
            *(uint4*)(Bs[nb] + sw_off(r0, c0)) = pb0;
            *(uint4*)(Bs[nb] + sw_off(r1, c1)) = pb1;
            __syncthreads();
            buf = nb;
        }
    }

    // epilogue: scale + store fp32
    #pragma unroll
    for (int tm = 0; tm < 2; ++tm) {
        #pragma unroll
        for (int t8 = 0; t8 < 8; ++t8) {
            int m = by * 128 + wm + tm * 16 + (lane >> 2);
            int n = bx * 128 + wn + t8 * 8 + (lane & 3) * 2;
            float2 lo = make_float2(acc[tm][t8][0] * alpha, acc[tm][t8][1] * alpha);
            float2 hi = make_float2(acc[tm][t8][2] * alpha, acc[tm][t8][3] * alpha);
            *(float2*)(Cb + (long long)m * SS + n)       = lo;
            *(float2*)(Cb + (long long)(m + 8) * SS + n) = hi;
        }
    }
}

// ---------------------------------------------------------------------------
// Per-query-row: top-48 candidates (approx score) -> exact fp64 rescore ->
// fp64 top-32 (tie -> lower index) -> softmax -> sparse AV.
// Phase 1 uses shuffle argmax: 2 syncthreads per round.
// ---------------------------------------------------------------------------
#define NEG_HUGE (-3.402823466e38f)
#define NEG_HUGE_D (-1e300)
#define SCALE_D (0.03125)

__global__ __launch_bounds__(256)
void topk_softmax_av(const float* __restrict__ scores,
                     const float* __restrict__ Q,
                     const float* __restrict__ Km,
                     const float* __restrict__ V,
                     float* __restrict__ ctx)
{
    const int r = blockIdx.x;
    const int b = r >> 11;
    const int tid  = threadIdx.x;
    const int lane = tid & 31;
    const int wid  = tid >> 5;

    __shared__ float  sc[SS];
    __shared__ float  qrow[DD];
    __shared__ float  wv[8];
    __shared__ int    wi_s[8];
    __shared__ int    gIdx;
    __shared__ int    cidx[NCAND];
    __shared__ double cval[NCAND];
    __shared__ float  selv[TOPK];
    __shared__ int    seli[TOPK];
    __shared__ float  prob[TOPK];

    const float* srow = scores + (long long)r * SS;
    for (int j = tid; j < SS; j += 256) sc[j] = srow[j];
    const float* qsrc = Q + (long long)r * DD;
    for (int j = tid; j < DD; j += 256) qrow[j] = qsrc[j];
    __syncthreads();

    // ---- Phase 1: top-48 candidates (iterated argmax, shuffle-based) ----
    float lmax = NEG_HUGE;
    int   lidx = tid * 16;
    {
        const int base = tid * 16;
        #pragma unroll
        for (int j = 0; j < 16; ++j) {
            float v = sc[base + j];
            if (v > lmax) { lmax = v; lidx = base + j; }
        }
    }

    for (int it = 0; it < NCAND; ++it) {
        float v = lmax; int ix = lidx;
        #pragma unroll
        for (int off = 16; off > 0; off >>= 1) {
            float ov = __shfl_xor_sync(0xffffffffu, v, off);
            int   oi = __shfl_xor_sync(0xffffffffu, ix, off);
            if (ov > v || (ov == v && oi < ix)) { v = ov; ix = oi; }
        }
        if (lane == 0) { wv[wid] = v; wi_s[wid] = ix; }
        __syncthreads();
        if (wid == 0) {
            float v8 = (lane < 8) ? wv[lane]   : NEG_HUGE;
            int   i8 = (lane < 8) ? wi_s[lane] : 0x7fffffff;
            #pragma unroll
            for (int off = 4; off > 0; off >>= 1) {
                float ov = __shfl_xor_sync(0xffffffffu, v8, off);
                int   oi = __shfl_xor_sync(0xffffffffu, i8, off);
                if (ov > v8 || (ov == v8 && oi < i8)) { v8 = ov; i8 = oi; }
            }
            if (lane == 0) { gIdx = i8; cidx[it] = i8; }
        }
        __syncthreads();
        const int gi = gIdx;
        if ((gi >> 4) == tid) {
            sc[gi] = NEG_HUGE;
            lmax = NEG_HUGE;
            const int base = tid * 16;
            lidx = base;
            #pragma unroll
            for (int j = 0; j < 16; ++j) {
                float vv = sc[base + j];
                if (vv > lmax) { lmax = vv; lidx = base + j; }
            }
        }
    }
    __syncthreads();

    // ---- Phase 2: exact fp64 rescore of 48 candidates ----
    const float* Kb = Km + (long long)b * SS * DD;
    for (int t = 0; t < 6; ++t) {
        const int c  = wid * 6 + t;
        const int mi = cidx[c];
        const float* krow = Kb + (long long)mi * DD;
        double s = 0.0;
        #pragma unroll 8
        for (int i = 0; i < 32; ++i) {
            int d = lane + 32 * i;
            s += (double)qrow[d] * (double)krow[d];
        }
        #pragma unroll
        for (int off = 16; off > 0; off >>= 1)
            s += __shfl_xor_sync(0xffffffffu, s, off);
        if (lane == 0) cval[c] = s;
    }
    __syncthreads();

    // ---- Phase 3: fp64 top-32 of 48, single-thread selection sort ----
    if (tid == 0) {
        bool used[NCAND];
        #pragma unroll
        for (int c = 0; c < NCAND; ++c) used[c] = false;
        for (int round = 0; round < TOPK; ++round) {
            double bv = NEG_HUGE_D; int bi = 0x7fffffff; int bc = 0;
            for (int c = 0; c < NCAND; ++c) {
                if (used[c]) continue;
                double v = cval[c]; int ix = cidx[c];
                if (v > bv || (v == bv && ix < bi)) { bv = v; bi = ix; bc = c; }
            }
            used[bc] = true;
            selv[round] = (float)(bv * SCALE_D);
            seli[round] = bi;
        }
    }
    __syncthreads();

    // ---- Phase 4: softmax over selected 32 ----
    if (tid < 32) {
        float e = expf(selv[tid] - selv[0]);
        float s = e;
        #pragma unroll
        for (int off = 16; off > 0; off >>= 1)
            s += __shfl_xor_sync(0xffffffffu, s, off);
        prob[tid] = e / s;
    }
    __syncthreads();

    // ---- Phase 5: ctx[r,:] = sum_i prob[i] * V[b, seli[i], :] ----
    const float* Vb = V + (long long)b * SS * DD;
    const int d = tid * 4;
    float4 accv = make_float4(0.f, 0.f, 0.f, 0.f);
    #pragma unroll 4
    for (int i = 0; i < TOPK; ++i) {
        const float p = prob[i];
        float4 v = *(const float4*)(Vb + (long long)seli[i] * DD + d);
        accv.x = fmaf(p, v.x, accv.x);
        accv.y = fmaf(p, v.y, accv.y);
        accv.z = fmaf(p, v.z, accv.z);
        accv.w = fmaf(p, v.w, accv.w);
    }
    *(float4*)(ctx + (long long)r * DD + d) = accv;
}

// ---------------------------------------------------------------------------
// Launch
// ---------------------------------------------------------------------------
extern "C" void kernel_launch(void* const* d_in, const int* in_sizes, int n_in,
                              void* d_out, int out_size)
{
    const float* query = (const float*)d_in[0];
    const float* mem   = (const float*)d_in[1];
    const float* Wq = (const float*)d_in[3];
    const float* bq = (const float*)d_in[4];
    const float* Wk = (const float*)d_in[5];
    const float* bk = (const float*)d_in[6];
    const float* Wv = (const float*)d_in[7];
    const float* bv = (const float*)d_in[8];
    const float* Wo = (const float*)d_in[9];
    const float* bo = (const float*)d_in[10];
    float* out = (float*)d_out;

    float *Q, *K, *V, *S, *CTX;
    __nv_bfloat16 *Qh, *Kh;
    cudaGetSymbolAddress((void**)&Q,   g_Q);
    cudaGetSymbolAddress((void**)&K,   g_K);
    cudaGetSymbolAddress((void**)&V,   g_V);
    cudaGetSymbolAddress((void**)&S,   g_S);
    cudaGetSymbolAddress((void**)&CTX, g_CTX);
    cudaGetSymbolAddress((void**)&Qh,  g_Qh);
    cudaGetSymbolAddress((void**)&Kh,  g_Kh);

    const float inv_sqrt_d = 1.0f / 32.0f;

    // Projections (fp32, FROZEN)
    gemm_nt<<<dim3(DD / BN, MQ  / BM, 1), 256>>>(query, Wq, Q, bq, MQ,  DD, DD, 1.f, 0, 0, 0);
    gemm_nt<<<dim3(DD / BN, MKV / BM, 1), 256>>>(mem,   Wk, K, bk, MKV, DD, DD, 1.f, 0, 0, 0);
    gemm_nt<<<dim3(DD / BN, MKV / BM, 1), 256>>>(mem,   Wv, V, bv, MKV, DD, DD, 1.f, 0, 0, 0);

    // Convert Q,K to bf16 for the candidate-scores GEMM
    f32_to_bf16_kernel<<<(MQ  * DD / 4 + 255) / 256, 256>>>(Q, Qh, MQ  * DD / 4);
    f32_to_bf16_kernel<<<(MKV * DD / 4 + 255) / 256, 256>>>(K, Kh, MKV * DD / 4);

    // Scores via bf16 tensor cores (candidate nomination only)
    gemm_nt_bf16_scores<<<dim3(SS / 128, TQ / 128, BATCH), 256>>>(Qh, Kh, S, inv_sqrt_d);

    // Top-48 -> exact fp64 rescore -> top-32 -> softmax -> sparse AV
    topk_softmax_av<<<MQ, 256>>>(S, Q, K, V, CTX);

    // Output projection (fp32)
    gemm_nt<<<dim3(DD / BN, MQ / BM, 1), 256>>>(CTX, Wo, out, bo, MQ, DD, DD, 1.f, 0, 0, 0);
}

// round 9
// speedup vs baseline: 1.5734x; 1.1484x over previous
#include <cuda_runtime.h>
#include <cuda_bf16.h>
#include <cstdint>

// ---------------------------------------------------------------------------
// SparseMemory read. Shapes: B=4, T=2048, S=4096, D=1024, TOPK=32. fp32 I/O.
//
// NUMERICS CONTRACT (validated rounds 6/7):
//  - Q/K projections: fp32 FFMA gemm_nt, FROZEN (fp64 rescore ground truth).
//  - Scores GEMM: candidate nomination only -> plain bf16 tensor cores OK.
//  - V/O projections: values only -> split-bf16 (hi+lo, 3 MMA terms, fp32
//    accum; rel err ~1e-5 << 1e-3 threshold).
//  - Selection: top-48 approx -> exact fp64 rescore -> fp64 top-32
//    (tie -> lower index). PRESERVED EXACTLY.
//
// R8 fix: split GEMM was 64KB STATIC smem (over 48KB cap -> compile fail).
// Now single-buffered: 4 tiles x 8KB = 32KB.
// ---------------------------------------------------------------------------

#define BATCH   4
#define TQ      2048
#define SS      4096
#define DD      1024
#define TOPK    32
#define NCAND   48

#define MQ      (BATCH*TQ)      // 8192
#define MKV     (BATCH*SS)      // 16384

__device__ float g_Q  [8192u  * 1024u];
__device__ float g_K  [16384u * 1024u];
__device__ float g_V  [16384u * 1024u];
__device__ float g_S  [33554432u];
__device__ float g_CTX[8192u  * 1024u];
__device__ __nv_bfloat16 g_Qh[8192u  * 1024u];
__device__ __nv_bfloat16 g_Kh[16384u * 1024u];
__device__ __nv_bfloat16 g_Mh[16384u * 1024u];
__device__ __nv_bfloat16 g_Ml[16384u * 1024u];
__device__ __nv_bfloat16 g_Ch[8192u  * 1024u];
__device__ __nv_bfloat16 g_Cl[8192u  * 1024u];
__device__ __nv_bfloat16 g_Wh[1024u * 1024u];
__device__ __nv_bfloat16 g_Wl[1024u * 1024u];

// ---------------------------------------------------------------------------
// fp32 tiled SGEMM (FROZEN for Q/K)
// ---------------------------------------------------------------------------
#define BM 128
#define BN 128
#define BK 16
#define TM 8
#define TN 8

__global__ __launch_bounds__(256, 2)
void gemm_nt(const float* __restrict__ A, const float* __restrict__ B,
             float* __restrict__ C, const float* __restrict__ bias,
             int M, int N, int Kd, float alpha,
             long long strideA, long long strideB, long long strideC)
{
    __shared__ float As[2][BK][BM];
    __shared__ float Bs[2][BK][BN];

    const int bx = blockIdx.x;
    const int by = blockIdx.y;
    const int bz = blockIdx.z;

    A += bz * strideA + (long long)by * BM * Kd;
    B += bz * strideB + (long long)bx * BN * Kd;
    C += bz * strideC;

    const int tid  = threadIdx.x;
    const int tx   = tid & 15;
    const int ty   = tid >> 4;
    const int lrow = tid >> 2;
    const int lcol = (tid & 3) * 4;

    float acc[TM][TN];
    #pragma unroll
    for (int i = 0; i < TM; ++i)
        #pragma unroll
        for (int j = 0; j < TN; ++j) acc[i][j] = 0.f;

    float4 pa[2], pb[2];

    #pragma unroll
    for (int r = 0; r < 2; ++r) {
        pa[r] = *(const float4*)(A + (long long)(lrow + r * 64) * Kd + lcol);
        pb[r] = *(const float4*)(B + (long long)(lrow + r * 64) * Kd + lcol);
    }
    #pragma unroll
    for (int r = 0; r < 2; ++r) {
        int row = lrow + r * 64;
        As[0][lcol + 0][row] = pa[r].x;
        As[0][lcol + 1][row] = pa[r].y;
        As[0][lcol + 2][row] = pa[r].z;
        As[0][lcol + 3][row] = pa[r].w;
        Bs[0][lcol + 0][row] = pb[r].x;
        Bs[0][lcol + 1][row] = pb[r].y;
        Bs[0][lcol + 2][row] = pb[r].z;
        Bs[0][lcol + 3][row] = pb[r].w;
    }
    __syncthreads();

    int buf = 0;
    for (int k0 = 0; k0 < Kd; k0 += BK) {
        const int k1 = k0 + BK;
        const bool more = (k1 < Kd);

        if (more) {
            #pragma unroll
            for (int r = 0; r < 2; ++r) {
                pa[r] = *(const float4*)(A + (long long)(lrow + r * 64) * Kd + k1 + lcol);
                pb[r] = *(const float4*)(B + (long long)(lrow + r * 64) * Kd + k1 + lcol);
            }
        }

        #pragma unroll
        for (int kk = 0; kk < BK; ++kk) {
            float a[TM], b[TN];
            *(float4*)&a[0] = *(const float4*)&As[buf][kk][ty * TM];
            *(float4*)&a[4] = *(const float4*)&As[buf][kk][ty * TM + 4];
            *(float4*)&b[0] = *(const float4*)&Bs[buf][kk][tx * TN];
            *(float4*)&b[4] = *(const float4*)&Bs[buf][kk][tx * TN + 4];
            #pragma unroll
            for (int i = 0; i < TM; ++i)
                #pragma unroll
                for (int j = 0; j < TN; ++j)
                    acc[i][j] = fmaf(a[i], b[j], acc[i][j]);
        }

        if (more) {
            const int nb = buf ^ 1;
            #pragma unroll
            for (int r = 0; r < 2; ++r) {
                int row = lrow + r * 64;
                As[nb][lcol + 0][row] = pa[r].x;
                As[nb][lcol + 1][row] = pa[r].y;
                As[nb][lcol + 2][row] = pa[r].z;
                As[nb][lcol + 3][row] = pa[r].w;
                Bs[nb][lcol + 0][row] = pb[r].x;
                Bs[nb][lcol + 1][row] = pb[r].y;
                Bs[nb][lcol + 2][row] = pb[r].z;
                Bs[nb][lcol + 3][row] = pb[r].w;
            }
            __syncthreads();
            buf = nb;
        }
    }

    #pragma unroll
    for (int i = 0; i < TM; ++i) {
        int row = by * BM + ty * TM + i;
        float* crow = C + (long long)row * N;
        #pragma unroll
        for (int j4 = 0; j4 < TN; j4 += 4) {
            int col = bx * BN + tx * TN + j4;
            float4 o;
            o.x = acc[i][j4 + 0] * alpha;
            o.y = acc[i][j4 + 1] * alpha;
            o.z = acc[i][j4 + 2] * alpha;
            o.w = acc[i][j4 + 3] * alpha;
            if (bias) {
                float4 bb = *(const float4*)(bias + col);
                o.x += bb.x; o.y += bb.y; o.z += bb.z; o.w += bb.w;
            }
            *(float4*)(crow + col) = o;
        }
    }
}

// ---------------------------------------------------------------------------
// Conversions
// ---------------------------------------------------------------------------
__global__ __launch_bounds__(256)
void f32_to_bf16_kernel(const float* __restrict__ in, __nv_bfloat16* __restrict__ out, int n4)
{
    int i = blockIdx.x * blockDim.x + threadIdx.x;
    if (i < n4) {
        float4 v = ((const float4*)in)[i];
        ((__nv_bfloat162*)out)[2 * i + 0] = __floats2bfloat162_rn(v.x, v.y);
        ((__nv_bfloat162*)out)[2 * i + 1] = __floats2bfloat162_rn(v.z, v.w);
    }
}

__global__ __launch_bounds__(256)
void f32_split_bf16_kernel(const float* __restrict__ in,
                           __nv_bfloat16* __restrict__ hi,
                           __nv_bfloat16* __restrict__ lo, int n4)
{
    int i = blockIdx.x * blockDim.x + threadIdx.x;
    if (i < n4) {
        float4 v = ((const float4*)in)[i];
        __nv_bfloat16 hx = __float2bfloat16_rn(v.x);
        __nv_bfloat16 hy = __float2bfloat16_rn(v.y);
        __nv_bfloat16 hz = __float2bfloat16_rn(v.z);
        __nv_bfloat16 hw = __float2bfloat16_rn(v.w);
        __nv_bfloat16 lx = __float2bfloat16_rn(v.x - __bfloat162float(hx));
        __nv_bfloat16 ly = __float2bfloat16_rn(v.y - __bfloat162float(hy));
        __nv_bfloat16 lz = __float2bfloat16_rn(v.z - __bfloat162float(hz));
        __nv_bfloat16 lw = __float2bfloat16_rn(v.w - __bfloat162float(hw));
        ((__nv_bfloat162*)hi)[2 * i + 0] = __nv_bfloat162(hx, hy);
        ((__nv_bfloat162*)hi)[2 * i + 1] = __nv_bfloat162(hz, hw);
        ((__nv_bfloat162*)lo)[2 * i + 0] = __nv_bfloat162(lx, ly);
        ((__nv_bfloat162*)lo)[2 * i + 1] = __nv_bfloat162(lz, lw);
    }
}

// ---------------------------------------------------------------------------
// bf16 MMA machinery
// ---------------------------------------------------------------------------
__device__ __forceinline__ uint32_t smem_u32p(const void* p) {
    return (uint32_t)__cvta_generic_to_shared(p);
}

__device__ __forceinline__ void ldsm_x4(uint32_t& r0, uint32_t& r1, uint32_t& r2, uint32_t& r3,
                                        uint32_t addr)
{
    asm volatile("ldmatrix.sync.aligned.m8n8.x4.shared.b16 {%0,%1,%2,%3}, [%4];"
                 : "=r"(r0), "=r"(r1), "=r"(r2), "=r"(r3) : "r"(addr));
}

__device__ __forceinline__ void mma_bf16(float* d, const uint32_t* a, uint32_t b0, uint32_t b1)
{
    asm volatile("mma.sync.aligned.m16n8k16.row.col.f32.bf16.bf16.f32 "
                 "{%0,%1,%2,%3}, {%4,%5,%6,%7}, {%8,%9}, {%0,%1,%2,%3};"
                 : "+f"(d[0]), "+f"(d[1]), "+f"(d[2]), "+f"(d[3])
                 : "r"(a[0]), "r"(a[1]), "r"(a[2]), "r"(a[3]), "r"(b0), "r"(b1));
}

__device__ __forceinline__ int sw_off(int r, int c) {
    int phys = ((c ^ r) & 3) ^ ((r >> 2) & 1);
    return r * 64 + phys * 16;
}

// ---------------------------------------------------------------------------
// bf16 scores GEMM (validated round 7; 32KB static smem)
// ---------------------------------------------------------------------------
__global__ __launch_bounds__(256)
void gemm_nt_bf16_scores(const __nv_bfloat16* __restrict__ A,
                         const __nv_bfloat16* __restrict__ Bm,
                         float* __restrict__ C, float alpha)
{
    __shared__ __align__(16) char As[2][128 * 64];
    __shared__ __align__(16) char Bs[2][128 * 64];

    const int bx = blockIdx.x;
    const int by = blockIdx.y;
    const int bz = blockIdx.z;

    const __nv_bfloat16* Ab = A  + (long long)bz * TQ * DD + (long long)by * 128 * DD;
    const __nv_bfloat16* Bb = Bm + (long long)bz * SS * DD + (long long)bx * 128 * DD;
    float* Cb = C + (long long)bz * TQ * SS;

    const int tid  = threadIdx.x;
    const int lane = tid & 31;
    const int wid  = tid >> 5;
    const int wm   = (wid & 3) * 32;
    const int wn   = (wid >> 2) * 64;

    const int r0 = tid >> 2,         c0 = tid & 3;
    const int r1 = (tid + 256) >> 2, c1 = (tid + 256) & 3;

    float acc[2][8][4];
    #pragma unroll
    for (int i = 0; i < 2; ++i)
        #pragma unroll
        for (int j = 0; j < 8; ++j)
            #pragma unroll
            for (int k = 0; k < 4; ++k) acc[i][j][k] = 0.f;

    uint4 pa0, pa1, pb0, pb1;

    pa0 = *(const uint4*)(Ab + (long long)r0 * DD + c0 * 8);
    pa1 = *(const uint4*)(Ab + (long long)r1 * DD + c1 * 8);
    pb0 = *(const uint4*)(Bb + (long long)r0 * DD + c0 * 8);
    pb1 = *(const uint4*)(Bb + (long long)r1 * DD + c1 * 8);
    *(uint4*)(As[0] + sw_off(r0, c0)) = pa0;
    *(uint4*)(As[0] + sw_off(r1, c1)) = pa1;
    *(uint4*)(Bs[0] + sw_off(r0, c0)) = pb0;
    *(uint4*)(Bs[0] + sw_off(r1, c1)) = pb1;
    __syncthreads();

    int buf = 0;
    for (int k0 = 0; k0 < DD; k0 += 32) {
        const int k1 = k0 + 32;
        const bool more = (k1 < DD);

        if (more) {
            pa0 = *(const uint4*)(Ab + (long long)r0 * DD + k1 + c0 * 8);
            pa1 = *(const uint4*)(Ab + (long long)r1 * DD + k1 + c1 * 8);
            pb0 = *(const uint4*)(Bb + (long long)r0 * DD + k1 + c0 * 8);
            pb1 = *(const uint4*)(Bb + (long long)r1 * DD + k1 + c1 * 8);
        }

        const uint32_t aBase = smem_u32p(As[buf]);
        const uint32_t bBase = smem_u32p(Bs[buf]);

        #pragma unroll
        for (int tk = 0; tk < 2; ++tk) {
            uint32_t afrag[2][4];
            #pragma unroll
            for (int tm = 0; tm < 2; ++tm) {
                int r = wm + tm * 16 + (lane & 7) + ((lane >> 3) & 1) * 8;
                int c = tk * 2 + (lane >> 4);
                ldsm_x4(afrag[tm][0], afrag[tm][1], afrag[tm][2], afrag[tm][3],
                        aBase + sw_off(r, c));
            }
            #pragma unroll
            for (int tn = 0; tn < 4; ++tn) {
                uint32_t bfrag[4];
                int r = wn + tn * 16 + (lane & 7) + ((lane >> 4) & 1) * 8;
                int c = tk * 2 + ((lane >> 3) & 1);
                ldsm_x4(bfrag[0], bfrag[1], bfrag[2], bfrag[3], bBase + sw_off(r, c));
                #pragma unroll
                for (int tm = 0; tm < 2; ++tm) {
                    mma_bf16(acc[tm][tn * 2 + 0], afrag[tm], bfrag[0], bfrag[1]);
                    mma_bf16(acc[tm][tn * 2 + 1], afrag[tm], bfrag[2], bfrag[3]);
                }
            }
        }

        if (more) {
            const int nb = buf ^ 1;
            *(uint4*)(As[nb] + sw_off(r0, c0)) = pa0;
            *(uint4*)(As[nb] + sw_off(r1, c1)) = pa1;
            *(uint4*)(Bs[nb] + sw_off(r0, c0)) = pb0;
            *(uint4*)(Bs[nb] + sw_off(r1, c1)) = pb1;
            __syncthreads();
            buf = nb;
        }
    }

    #pragma unroll
    for (int tm = 0; tm < 2; ++tm) {
        #pragma unroll
        for (int t8 = 0; t8 < 8; ++t8) {
            int m = by * 128 + wm + tm * 16 + (lane >> 2);
            int n = bx * 128 + wn + t8 * 8 + (lane & 3) * 2;
            float2 lo = make_float2(acc[tm][t8][0] * alpha, acc[tm][t8][1] * alpha);
            float2 hi = make_float2(acc[tm][t8][2] * alpha, acc[tm][t8][3] * alpha);
            *(float2*)(Cb + (long long)m * SS + n)       = lo;
            *(float2*)(Cb + (long long)(m + 8) * SS + n) = hi;
        }
    }
}

// ---------------------------------------------------------------------------
// split-bf16 GEMM (V and O projections; values only)
// SINGLE-buffered: 4 tiles x 8KB = 32KB static smem (under 48KB cap).
// C = Ahi*Bhi^T + Ahi*Blo^T + Alo*Bhi^T + bias, fp32 accum.
// ---------------------------------------------------------------------------
__global__ __launch_bounds__(256)
void gemm_nt_bf16_split(const __nv_bfloat16* __restrict__ Ah,
                        const __nv_bfloat16* __restrict__ Al,
                        const __nv_bfloat16* __restrict__ Bh,
                        const __nv_bfloat16* __restrict__ Bl,
                        float* __restrict__ C, const float* __restrict__ bias)
{
    __shared__ __align__(16) char Ash[128 * 64];
    __shared__ __align__(16) char Asl[128 * 64];
    __shared__ __align__(16) char Bsh[128 * 64];
    __shared__ __align__(16) char Bsl[128 * 64];

    const int bx = blockIdx.x;
    const int by = blockIdx.y;

    const __nv_bfloat16* Ahb = Ah + (long long)by * 128 * DD;
    const __nv_bfloat16* Alb = Al + (long long)by * 128 * DD;
    const __nv_bfloat16* Bhb = Bh + (long long)bx * 128 * DD;
    const __nv_bfloat16* Blb = Bl + (long long)bx * 128 * DD;

    const int tid  = threadIdx.x;
    const int lane = tid & 31;
    const int wid  = tid >> 5;
    const int wm   = (wid & 3) * 32;
    const int wn   = (wid >> 2) * 64;

    const int r0 = tid >> 2,         c0 = tid & 3;
    const int r1 = (tid + 256) >> 2, c1 = (tid + 256) & 3;

    float acc[2][8][4];
    #pragma unroll
    for (int i = 0; i < 2; ++i)
        #pragma unroll
        for (int j = 0; j < 8; ++j)
            #pragma unroll
            for (int k = 0; k < 4; ++k) acc[i][j][k] = 0.f;

    for (int k0 = 0; k0 < DD; k0 += 32) {
        // load this k-tile (prefetch into regs first to batch the LDGs)
        uint4 pah0 = *(const uint4*)(Ahb + (long long)r0 * DD + k0 + c0 * 8);
        uint4 pah1 = *(const uint4*)(Ahb + (long long)r1 * DD + k0 + c1 * 8);
        uint4 pal0 = *(const uint4*)(Alb + (long long)r0 * DD + k0 + c0 * 8);
        uint4 pal1 = *(const uint4*)(Alb + (long long)r1 * DD + k0 + c1 * 8);
        uint4 pbh0 = *(const uint4*)(Bhb + (long long)r0 * DD + k0 + c0 * 8);
        uint4 pbh1 = *(const uint4*)(Bhb + (long long)r1 * DD + k0 + c1 * 8);
        uint4 pbl0 = *(const uint4*)(Blb + (long long)r0 * DD + k0 + c0 * 8);
        uint4 pbl1 = *(const uint4*)(Blb + (long long)r1 * DD + k0 + c1 * 8);
        *(uint4*)(Ash + sw_off(r0, c0)) = pah0;
        *(uint4*)(Ash + sw_off(r1, c1)) = pah1;
        *(uint4*)(Asl + sw_off(r0, c0)) = pal0;
        *(uint4*)(Asl + sw_off(r1, c1)) = pal1;
        *(uint4*)(Bsh + sw_off(r0, c0)) = pbh0;
        *(uint4*)(Bsh + sw_off(r1, c1)) = pbh1;
        *(uint4*)(Bsl + sw_off(r0, c0)) = pbl0;
        *(uint4*)(Bsl + sw_off(r1, c1)) = pbl1;
        __syncthreads();

        const uint32_t ahB = smem_u32p(Ash);
        const uint32_t alB = smem_u32p(Asl);
        const uint32_t bhB = smem_u32p(Bsh);
        const uint32_t blB = smem_u32p(Bsl);

        #pragma unroll
        for (int tk = 0; tk < 2; ++tk) {
            uint32_t ah[2][4], al[2][4];
            #pragma unroll
            for (int tm = 0; tm < 2; ++tm) {
                int r = wm + tm * 16 + (lane & 7) + ((lane >> 3) & 1) * 8;
                int c = tk * 2 + (lane >> 4);
                ldsm_x4(ah[tm][0], ah[tm][1], ah[tm][2], ah[tm][3], ahB + sw_off(r, c));
                ldsm_x4(al[tm][0], al[tm][1], al[tm][2], al[tm][3], alB + sw_off(r, c));
            }
            #pragma unroll
            for (int tn = 0; tn < 4; ++tn) {
                uint32_t bh[4], bl[4];
                int r = wn + tn * 16 + (lane & 7) + ((lane >> 4) & 1) * 8;
                int c = tk * 2 + ((lane >> 3) & 1);
                ldsm_x4(bh[0], bh[1], bh[2], bh[3], bhB + sw_off(r, c));
                ldsm_x4(bl[0], bl[1], bl[2], bl[3], blB + sw_off(r, c));
                #pragma unroll
                for (int tm = 0; tm < 2; ++tm) {
                    mma_bf16(acc[tm][tn * 2 + 0], ah[tm], bh[0], bh[1]);
                    mma_bf16(acc[tm][tn * 2 + 1], ah[tm], bh[2], bh[3]);
                    mma_bf16(acc[tm][tn * 2 + 0], ah[tm], bl[0], bl[1]);
                    mma_bf16(acc[tm][tn * 2 + 1], ah[tm], bl[2], bl[3]);
                    mma_bf16(acc[tm][tn * 2 + 0], al[tm], bh[0], bh[1]);
                    mma_bf16(acc[tm][tn * 2 + 1], al[tm], bh[2], bh[3]);
                }
            }
        }
        __syncthreads();
    }

    #pragma unroll
    for (int tm = 0; tm < 2; ++tm) {
        #pragma unroll
        for (int t8 = 0; t8 < 8; ++t8) {
            int m = by * 128 + wm + tm * 16 + (lane >> 2);
            int n = bx * 128 + wn + t8 * 8 + (lane & 3) * 2;
            float2 bb = *(const float2*)(bias + n);
            float2 lo = make_float2(acc[tm][t8][0] + bb.x, acc[tm][t8][1] + bb.y);
            float2 hi = make_float2(acc[tm][t8][2] + bb.x, acc[tm][t8][3] + bb.y);
            *(float2*)(C + (long long)m * DD + n)       = lo;
            *(float2*)(C + (long long)(m + 8) * DD + n) = hi;
        }
    }
}

// ---------------------------------------------------------------------------
// top-k kernel (validated rounds 6/7 — unchanged)
// ---------------------------------------------------------------------------
#define NEG_HUGE (-3.402823466e38f)
#define NEG_HUGE_D (-1e300)
#define SCALE_D (0.03125)

__global__ __launch_bounds__(256)
void topk_softmax_av(const float* __restrict__ scores,
                     const float* __restrict__ Q,
                     const float* __restrict__ Km,
                     const float* __restrict__ V,
                     float* __restrict__ ctx)
{
    const int r = blockIdx.x;
    const int b = r >> 11;
    const int tid  = threadIdx.x;
    const int lane = tid & 31;
    const int wid  = tid >> 5;

    __shared__ float  sc[SS];
    __shared__ float  qrow[DD];
    __shared__ float  wv[8];
    __shared__ int    wi_s[8];
    __shared__ int    gIdx;
    __shared__ int    cidx[NCAND];
    __shared__ double cval[NCAND];
    __shared__ float  selv[TOPK];
    __shared__ int    seli[TOPK];
    __shared__ float  prob[TOPK];

    const float* srow = scores + (long long)r * SS;
    for (int j = tid; j < SS; j += 256) sc[j] = srow[j];
    const float* qsrc = Q + (long long)r * DD;
    for (int j = tid; j < DD; j += 256) qrow[j] = qsrc[j];
    __syncthreads();

    float lmax = NEG_HUGE;
    int   lidx = tid * 16;
    {
        const int base = tid * 16;
        #pragma unroll
        for (int j = 0; j < 16; ++j) {
            float v = sc[base + j];
            if (v > lmax) { lmax = v; lidx = base + j; }
        }
    }

    for (int it = 0; it < NCAND; ++it) {
        float v = lmax; int ix = lidx;
        #pragma unroll
        for (int off = 16; off > 0; off >>= 1) {
            float ov = __shfl_xor_sync(0xffffffffu, v, off);
            int   oi = __shfl_xor_sync(0xffffffffu, ix, off);
            if (ov > v || (ov == v && oi < ix)) { v = ov; ix = oi; }
        }
        if (lane == 0) { wv[wid] = v; wi_s[wid] = ix; }
        __syncthreads();
        if (wid == 0) {
            float v8 = (lane < 8) ? wv[lane]   : NEG_HUGE;
            int   i8 = (lane < 8) ? wi_s[lane] : 0x7fffffff;
            #pragma unroll
            for (int off = 4; off > 0; off >>= 1) {
                float ov = __shfl_xor_sync(0xffffffffu, v8, off);
                int   oi = __shfl_xor_sync(0xffffffffu, i8, off);
                if (ov > v8 || (ov == v8 && oi < i8)) { v8 = ov; i8 = oi; }
            }
            if (lane == 0) { gIdx = i8; cidx[it] = i8; }
        }
        __syncthreads();
        const int gi = gIdx;
        if ((gi >> 4) == tid) {
            sc[gi] = NEG_HUGE;
            lmax = NEG_HUGE;
            const int base = tid * 16;
            lidx = base;
            #pragma unroll
            for (int j = 0; j < 16; ++j) {
                float vv = sc[base + j];
                if (vv > lmax) { lmax = vv; lidx = base + j; }
            }
        }
    }
    __syncthreads();

    const float* Kb = Km + (long long)b * SS * DD;
    for (int t = 0; t < 6; ++t) {
        const int c  = wid * 6 + t;
        const int mi = cidx[c];
        const float* krow = Kb + (long long)mi * DD;
        double s = 0.0;
        #pragma unroll 8
        for (int i = 0; i < 32; ++i) {
            int d = lane + 32 * i;
            s += (double)qrow[d] * (double)krow[d];
        }
        #pragma unroll
        for (int off = 16; off > 0; off >>= 1)
            s += __shfl_xor_sync(0xffffffffu, s, off);
        if (lane == 0) cval[c] = s;
    }
    __syncthreads();

    if (tid == 0) {
        bool used[NCAND];
        #pragma unroll
        for (int c = 0; c < NCAND; ++c) used[c] = false;
        for (int round = 0; round < TOPK; ++round) {
            double bv = NEG_HUGE_D; int bi = 0x7fffffff; int bc = 0;
            for (int c = 0; c < NCAND; ++c) {
                if (used[c]) continue;
                double v = cval[c]; int ix = cidx[c];
                if (v > bv || (v == bv && ix < bi)) { bv = v; bi = ix; bc = c; }
            }
            used[bc] = true;
            selv[round] = (float)(bv * SCALE_D);
            seli[round] = bi;
        }
    }
    __syncthreads();

    if (tid < 32) {
        float e = expf(selv[tid] - selv[0]);
        float s = e;
        #pragma unroll
        for (int off = 16; off > 0; off >>= 1)
            s += __shfl_xor_sync(0xffffffffu, s, off);
        prob[tid] = e / s;
    }
    __syncthreads();

    const float* Vb = V + (long long)b * SS * DD;
    const int d = tid * 4;
    float4 accv = make_float4(0.f, 0.f, 0.f, 0.f);
    #pragma unroll 4
    for (int i = 0; i < TOPK; ++i) {
        const float p = prob[i];
        float4 v = *(const float4*)(Vb + (long long)seli[i] * DD + d);
        accv.x = fmaf(p, v.x, accv.x);
        accv.y = fmaf(p, v.y, accv.y);
        accv.z = fmaf(p, v.z, accv.z);
        accv.w = fmaf(p, v.w, accv.w);
    }
    *(float4*)(ctx + (long long)r * DD + d) = accv;
}

// ---------------------------------------------------------------------------
// Launch
// ---------------------------------------------------------------------------
extern "C" void kernel_launch(void* const* d_in, const int* in_sizes, int n_in,
                              void* d_out, int out_size)
{
    const float* query = (const float*)d_in[0];
    const float* mem   = (const float*)d_in[1];
    const float* Wq = (const float*)d_in[3];
    const float* bq = (const float*)d_in[4];
    const float* Wk = (const float*)d_in[5];
    const float* bk = (const float*)d_in[6];
    const float* Wv = (const float*)d_in[7];
    const float* bv = (const float*)d_in[8];
    const float* Wo = (const float*)d_in[9];
    const float* bo = (const float*)d_in[10];
    float* out = (float*)d_out;

    float *Q, *K, *V, *S, *CTX;
    __nv_bfloat16 *Qh, *Kh, *Mh, *Ml, *Ch, *Cl, *Wh, *Wl;
    cudaGetSymbolAddress((void**)&Q,   g_Q);
    cudaGetSymbolAddress((void**)&K,   g_K);
    cudaGetSymbolAddress((void**)&V,   g_V);
    cudaGetSymbolAddress((void**)&S,   g_S);
    cudaGetSymbolAddress((void**)&CTX, g_CTX);
    cudaGetSymbolAddress((void**)&Qh,  g_Qh);
    cudaGetSymbolAddress((void**)&Kh,  g_Kh);
    cudaGetSymbolAddress((void**)&Mh,  g_Mh);
    cudaGetSymbolAddress((void**)&Ml,  g_Ml);
    cudaGetSymbolAddress((void**)&Ch,  g_Ch);
    cudaGetSymbolAddress((void**)&Cl,  g_Cl);
    cudaGetSymbolAddress((void**)&Wh,  g_Wh);
    cudaGetSymbolAddress((void**)&Wl,  g_Wl);

    const float inv_sqrt_d = 1.0f / 32.0f;

    // Q/K projections (fp32, FROZEN)
    gemm_nt<<<dim3(DD / BN, MQ  / BM, 1), 256>>>(query, Wq, Q, bq, MQ,  DD, DD, 1.f, 0, 0, 0);
    gemm_nt<<<dim3(DD / BN, MKV / BM, 1), 256>>>(mem,   Wk, K, bk, MKV, DD, DD, 1.f, 0, 0, 0);

    // V projection via split-bf16 tensor cores (values only)
    f32_split_bf16_kernel<<<(MKV * DD / 4 + 255) / 256, 256>>>(mem, Mh, Ml, MKV * DD / 4);
    f32_split_bf16_kernel<<<(DD  * DD / 4 + 255) / 256, 256>>>(Wv,  Wh, Wl, DD  * DD / 4);
    gemm_nt_bf16_split<<<dim3(DD / 128, MKV / 128), 256>>>(Mh, Ml, Wh, Wl, V, bv);

    // Scores (candidate nomination): plain bf16 tensor cores
    f32_to_bf16_kernel<<<(MQ  * DD / 4 + 255) / 256, 256>>>(Q, Qh, MQ  * DD / 4);
    f32_to_bf16_kernel<<<(MKV * DD / 4 + 255) / 256, 256>>>(K, Kh, MKV * DD / 4);
    gemm_nt_bf16_scores<<<dim3(SS / 128, TQ / 128, BATCH), 256>>>(Qh, Kh, S, inv_sqrt_d);

    // Top-48 -> exact fp64 rescore -> top-32 -> softmax -> sparse AV
    topk_softmax_av<<<MQ, 256>>>(S, Q, K, V, CTX);

    // O projection via split-bf16 tensor cores (reuse weight split buffers)
    f32_split_bf16_kernel<<<(MQ * DD / 4 + 255) / 256, 256>>>(CTX, Ch, Cl, MQ * DD / 4);
    f32_split_bf16_kernel<<<(DD * DD / 4 + 255) / 256, 256>>>(Wo,  Wh, Wl, DD * DD / 4);
    gemm_nt_bf16_split<<<dim3(DD / 128, MQ / 128), 256>>>(Ch, Cl, Wh, Wl, out, bo);
}

// round 10
// speedup vs baseline: 3.1070x; 1.9747x over previous
#include <cuda_runtime.h>
#include <cuda_bf16.h>
#include <cstdint>

// ---------------------------------------------------------------------------
// SparseMemory read. Shapes: B=4, T=2048, S=4096, D=1024, TOPK=32. fp32 I/O.
//
// NUMERICS CONTRACT (validated rounds 6/7/9):
//  - Q/K projections: fp32 FFMA gemm_nt, accumulation chain FROZEN (the fp64
//    rescore treats these q,k as ground truth). bf16 epilogue stores added
//    (values unchanged).
//  - Scores GEMM: candidate nomination only -> plain bf16 tensor cores.
//  - V/O projections: split-bf16 (hi+lo, 3 MMA terms, fp32 accum).
//  - Selection: candidate pool (superset of top-48 by approx score, via
//    histogram threshold) -> exact fp64 rescore -> exact fp64 top-32 by rank
//    (tie -> lower index). Output identical to iterated-argmax version.
// ---------------------------------------------------------------------------

#define BATCH   4
#define TQ      2048
#define SS      4096
#define DD      1024
#define TOPK    32
#define NCAND   48
#define MAXPOOL 128

#define MQ      (BATCH*TQ)      // 8192
#define MKV     (BATCH*SS)      // 16384

__device__ float g_Q  [8192u  * 1024u];
__device__ float g_K  [16384u * 1024u];
__device__ float g_V  [16384u * 1024u];
__device__ float g_S  [33554432u];
__device__ float g_CTX[8192u  * 1024u];
__device__ __nv_bfloat16 g_Qh[8192u  * 1024u];
__device__ __nv_bfloat16 g_Kh[16384u * 1024u];
__device__ __nv_bfloat16 g_Mh[16384u * 1024u];
__device__ __nv_bfloat16 g_Ml[16384u * 1024u];
__device__ __nv_bfloat16 g_Ch[8192u  * 1024u];
__device__ __nv_bfloat16 g_Cl[8192u  * 1024u];
__device__ __nv_bfloat16 g_Wh[1024u * 1024u];
__device__ __nv_bfloat16 g_Wl[1024u * 1024u];

// ---------------------------------------------------------------------------
// fp32 tiled SGEMM (FROZEN accumulation; optional fused bf16 output)
// ---------------------------------------------------------------------------
#define BM 128
#define BN 128
#define BK 16
#define TM 8
#define TN 8

__global__ __launch_bounds__(256, 2)
void gemm_nt(const float* __restrict__ A, const float* __restrict__ B,
             float* __restrict__ C, __nv_bfloat16* __restrict__ Cbf,
             const float* __restrict__ bias,
             int M, int N, int Kd, float alpha,
             long long strideA, long long strideB, long long strideC)
{
    __shared__ float As[2][BK][BM];
    __shared__ float Bs[2][BK][BN];

    const int bx = blockIdx.x;
    const int by = blockIdx.y;
    const int bz = blockIdx.z;

    A += bz * strideA + (long long)by * BM * Kd;
    B += bz * strideB + (long long)bx * BN * Kd;
    C += bz * strideC;
    if (Cbf) Cbf += bz * strideC;

    const int tid  = threadIdx.x;
    const int tx   = tid & 15;
    const int ty   = tid >> 4;
    const int lrow = tid >> 2;
    const int lcol = (tid & 3) * 4;

    float acc[TM][TN];
    #pragma unroll
    for (int i = 0; i < TM; ++i)
        #pragma unroll
        for (int j = 0; j < TN; ++j) acc[i][j] = 0.f;

    float4 pa[2], pb[2];

    #pragma unroll
    for (int r = 0; r < 2; ++r) {
        pa[r] = *(const float4*)(A + (long long)(lrow + r * 64) * Kd + lcol);
        pb[r] = *(const float4*)(B + (long long)(lrow + r * 64) * Kd + lcol);
    }
    #pragma unroll
    for (int r = 0; r < 2; ++r) {
        int row = lrow + r * 64;
        As[0][lcol + 0][row] = pa[r].x;
        As[0][lcol + 1][row] = pa[r].y;
        As[0][lcol + 2][row] = pa[r].z;
        As[0][lcol + 3][row] = pa[r].w;
        Bs[0][lcol + 0][row] = pb[r].x;
        Bs[0][lcol + 1][row] = pb[r].y;
        Bs[0][lcol + 2][row] = pb[r].z;
        Bs[0][lcol + 3][row] = pb[r].w;
    }
    __syncthreads();

    int buf = 0;
    for (int k0 = 0; k0 < Kd; k0 += BK) {
        const int k1 = k0 + BK;
        const bool more = (k1 < Kd);

        if (more) {
            #pragma unroll
            for (int r = 0; r < 2; ++r) {
                pa[r] = *(const float4*)(A + (long long)(lrow + r * 64) * Kd + k1 + lcol);
                pb[r] = *(const float4*)(B + (long long)(lrow + r * 64) * Kd + k1 + lcol);
            }
        }

        #pragma unroll
        for (int kk = 0; kk < BK; ++kk) {
            float a[TM], b[TN];
            *(float4*)&a[0] = *(const float4*)&As[buf][kk][ty * TM];
            *(float4*)&a[4] = *(const float4*)&As[buf][kk][ty * TM + 4];
            *(float4*)&b[0] = *(const float4*)&Bs[buf][kk][tx * TN];
            *(float4*)&b[4] = *(const float4*)&Bs[buf][kk][tx * TN + 4];
            #pragma unroll
            for (int i = 0; i < TM; ++i)
                #pragma unroll
                for (int j = 0; j < TN; ++j)
                    acc[i][j] = fmaf(a[i], b[j], acc[i][j]);
        }

        if (more) {
            const int nb = buf ^ 1;
            #pragma unroll
            for (int r = 0; r < 2; ++r) {
                int row = lrow + r * 64;
                As[nb][lcol + 0][row] = pa[r].x;
                As[nb][lcol + 1][row] = pa[r].y;
                As[nb][lcol + 2][row] = pa[r].z;
                As[nb][lcol + 3][row] = pa[r].w;
                Bs[nb][lcol + 0][row] = pb[r].x;
                Bs[nb][lcol + 1][row] = pb[r].y;
                Bs[nb][lcol + 2][row] = pb[r].z;
                Bs[nb][lcol + 3][row] = pb[r].w;
            }
            __syncthreads();
            buf = nb;
        }
    }

    #pragma unroll
    for (int i = 0; i < TM; ++i) {
        int row = by * BM + ty * TM + i;
        float* crow = C + (long long)row * N;
        #pragma unroll
        for (int j4 = 0; j4 < TN; j4 += 4) {
            int col = bx * BN + tx * TN + j4;
            float4 o;
            o.x = acc[i][j4 + 0] * alpha;
            o.y = acc[i][j4 + 1] * alpha;
            o.z = acc[i][j4 + 2] * alpha;
            o.w = acc[i][j4 + 3] * alpha;
            if (bias) {
                float4 bb = *(const float4*)(bias + col);
                o.x += bb.x; o.y += bb.y; o.z += bb.z; o.w += bb.w;
            }
            *(float4*)(crow + col) = o;
            if (Cbf) {
                __nv_bfloat162* brow = (__nv_bfloat162*)(Cbf + (long long)row * N + col);
                brow[0] = __floats2bfloat162_rn(o.x, o.y);
                brow[1] = __floats2bfloat162_rn(o.z, o.w);
            }
        }
    }
}

// ---------------------------------------------------------------------------
// Conversions
// ---------------------------------------------------------------------------
__global__ __launch_bounds__(256)
void f32_split_bf16_kernel(const float* __restrict__ in,
                           __nv_bfloat16* __restrict__ hi,
                           __nv_bfloat16* __restrict__ lo, int n4)
{
    int i = blockIdx.x * blockDim.x + threadIdx.x;
    if (i < n4) {
        float4 v = ((const float4*)in)[i];
        __nv_bfloat16 hx = __float2bfloat16_rn(v.x);
        __nv_bfloat16 hy = __float2bfloat16_rn(v.y);
        __nv_bfloat16 hz = __float2bfloat16_rn(v.z);
        __nv_bfloat16 hw = __float2bfloat16_rn(v.w);
        __nv_bfloat16 lx = __float2bfloat16_rn(v.x - __bfloat162float(hx));
        __nv_bfloat16 ly = __float2bfloat16_rn(v.y - __bfloat162float(hy));
        __nv_bfloat16 lz = __float2bfloat16_rn(v.z - __bfloat162float(hz));
        __nv_bfloat16 lw = __float2bfloat16_rn(v.w - __bfloat162float(hw));
        ((__nv_bfloat162*)hi)[2 * i + 0] = __nv_bfloat162(hx, hy);
        ((__nv_bfloat162*)hi)[2 * i + 1] = __nv_bfloat162(hz, hw);
        ((__nv_bfloat162*)lo)[2 * i + 0] = __nv_bfloat162(lx, ly);
        ((__nv_bfloat162*)lo)[2 * i + 1] = __nv_bfloat162(lz, lw);
    }
}

// ---------------------------------------------------------------------------
// bf16 MMA machinery
// ---------------------------------------------------------------------------
__device__ __forceinline__ uint32_t smem_u32p(const void* p) {
    return (uint32_t)__cvta_generic_to_shared(p);
}

__device__ __forceinline__ void ldsm_x4(uint32_t& r0, uint32_t& r1, uint32_t& r2, uint32_t& r3,
                                        uint32_t addr)
{
    asm volatile("ldmatrix.sync.aligned.m8n8.x4.shared.b16 {%0,%1,%2,%3}, [%4];"
                 : "=r"(r0), "=r"(r1), "=r"(r2), "=r"(r3) : "r"(addr));
}

__device__ __forceinline__ void mma_bf16(float* d, const uint32_t* a, uint32_t b0, uint32_t b1)
{
    asm volatile("mma.sync.aligned.m16n8k16.row.col.f32.bf16.bf16.f32 "
                 "{%0,%1,%2,%3}, {%4,%5,%6,%7}, {%8,%9}, {%0,%1,%2,%3};"
                 : "+f"(d[0]), "+f"(d[1]), "+f"(d[2]), "+f"(d[3])
                 : "r"(a[0]), "r"(a[1]), "r"(a[2]), "r"(a[3]), "r"(b0), "r"(b1));
}

__device__ __forceinline__ int sw_off(int r, int c) {
    int phys = ((c ^ r) & 3) ^ ((r >> 2) & 1);
    return r * 64 + phys * 16;
}

// ---------------------------------------------------------------------------
// bf16 scores GEMM (validated; 32KB static smem)
// ---------------------------------------------------------------------------
__global__ __launch_bounds__(256)
void gemm_nt_bf16_scores(const __nv_bfloat16* __restrict__ A,
                         const __nv_bfloat16* __restrict__ Bm,
                         float* __restrict__ C, float alpha)
{
    __shared__ __align__(16) char As[2][128 * 64];
    __shared__ __align__(16) char Bs[2][128 * 64];

    const int bx = blockIdx.x;
    const int by = blockIdx.y;
    const int bz = blockIdx.z;

    const __nv_bfloat16* Ab = A  + (long long)bz * TQ * DD + (long long)by * 128 * DD;
    const __nv_bfloat16* Bb = Bm + (long long)bz * SS * DD + (long long)bx * 128 * DD;
    float* Cb = C + (long long)bz * TQ * SS;

    const int tid  = threadIdx.x;
    const int lane = tid & 31;
    const int wid  = tid >> 5;
    const int wm   = (wid & 3) * 32;
    const int wn   = (wid >> 2) * 64;

    const int r0 = tid >> 2,         c0 = tid & 3;
    const int r1 = (tid + 256) >> 2, c1 = (tid + 256) & 3;

    float acc[2][8][4];
    #pragma unroll
    for (int i = 0; i < 2; ++i)
        #pragma unroll
        for (int j = 0; j < 8; ++j)
            #pragma unroll
            for (int k = 0; k < 4; ++k) acc[i][j][k] = 0.f;

    uint4 pa0, pa1, pb0, pb1;

    pa0 = *(const uint4*)(Ab + (long long)r0 * DD + c0 * 8);
    pa1 = *(const uint4*)(Ab + (long long)r1 * DD + c1 * 8);
    pb0 = *(const uint4*)(Bb + (long long)r0 * DD + c0 * 8);
    pb1 = *(const uint4*)(Bb + (long long)r1 * DD + c1 * 8);
    *(uint4*)(As[0] + sw_off(r0, c0)) = pa0;
    *(uint4*)(As[0] + sw_off(r1, c1)) = pa1;
    *(uint4*)(Bs[0] + sw_off(r0, c0)) = pb0;
    *(uint4*)(Bs[0] + sw_off(r1, c1)) = pb1;
    __syncthreads();

    int buf = 0;
    for (int k0 = 0; k0 < DD; k0 += 32) {
        const int k1 = k0 + 32;
        const bool more = (k1 < DD);

        if (more) {
            pa0 = *(const uint4*)(Ab + (long long)r0 * DD + k1 + c0 * 8);
            pa1 = *(const uint4*)(Ab + (long long)r1 * DD + k1 + c1 * 8);
            pb0 = *(const uint4*)(Bb + (long long)r0 * DD + k1 + c0 * 8);
            pb1 = *(const uint4*)(Bb + (long long)r1 * DD + k1 + c1 * 8);
        }

        const uint32_t aBase = smem_u32p(As[buf]);
        const uint32_t bBase = smem_u32p(Bs[buf]);

        #pragma unroll
        for (int tk = 0; tk < 2; ++tk) {
            uint32_t afrag[2][4];
            #pragma unroll
            for (int tm = 0; tm < 2; ++tm) {
                int r = wm + tm * 16 + (lane & 7) + ((lane >> 3) & 1) * 8;
                int c = tk * 2 + (lane >> 4);
                ldsm_x4(afrag[tm][0], afrag[tm][1], afrag[tm][2], afrag[tm][3],
                        aBase + sw_off(r, c));
            }
            #pragma unroll
            for (int tn = 0; tn < 4; ++tn) {
                uint32_t bfrag[4];
                int r = wn + tn * 16 + (lane & 7) + ((lane >> 4) & 1) * 8;
                int c = tk * 2 + ((lane >> 3) & 1);
                ldsm_x4(bfrag[0], bfrag[1], bfrag[2], bfrag[3], bBase + sw_off(r, c));
                #pragma unroll
                for (int tm = 0; tm < 2; ++tm) {
                    mma_bf16(acc[tm][tn * 2 + 0], afrag[tm], bfrag[0], bfrag[1]);
                    mma_bf16(acc[tm][tn * 2 + 1], afrag[tm], bfrag[2], bfrag[3]);
                }
            }
        }

        if (more) {
            const int nb = buf ^ 1;
            *(uint4*)(As[nb] + sw_off(r0, c0)) = pa0;
            *(uint4*)(As[nb] + sw_off(r1, c1)) = pa1;
            *(uint4*)(Bs[nb] + sw_off(r0, c0)) = pb0;
            *(uint4*)(Bs[nb] + sw_off(r1, c1)) = pb1;
            __syncthreads();
            buf = nb;
        }
    }

    #pragma unroll
    for (int tm = 0; tm < 2; ++tm) {
        #pragma unroll
        for (int t8 = 0; t8 < 8; ++t8) {
            int m = by * 128 + wm + tm * 16 + (lane >> 2);
            int n = bx * 128 + wn + t8 * 8 + (lane & 3) * 2;
            float2 lo = make_float2(acc[tm][t8][0] * alpha, acc[tm][t8][1] * alpha);
            float2 hi = make_float2(acc[tm][t8][2] * alpha, acc[tm][t8][3] * alpha);
            *(float2*)(Cb + (long long)m * SS + n)       = lo;
            *(float2*)(Cb + (long long)(m + 8) * SS + n) = hi;
        }
    }
}

// ---------------------------------------------------------------------------
// split-bf16 GEMM (V and O projections; values only). 32KB static smem.
// ---------------------------------------------------------------------------
__global__ __launch_bounds__(256)
void gemm_nt_bf16_split(const __nv_bfloat16* __restrict__ Ah,
                        const __nv_bfloat16* __restrict__ Al,
                        const __nv_bfloat16* __restrict__ Bh,
                        const __nv_bfloat16* __restrict__ Bl,
                        float* __restrict__ C, const float* __restrict__ bias)
{
    __shared__ __align__(16) char Ash[128 * 64];
    __shared__ __align__(16) char Asl[128 * 64];
    __shared__ __align__(16) char Bsh[128 * 64];
    __shared__ __align__(16) char Bsl[128 * 64];

    const int bx = blockIdx.x;
    const int by = blockIdx.y;

    const __nv_bfloat16* Ahb = Ah + (long long)by * 128 * DD;
    const __nv_bfloat16* Alb = Al + (long long)by * 128 * DD;
    const __nv_bfloat16* Bhb = Bh + (long long)bx * 128 * DD;
    const __nv_bfloat16* Blb = Bl + (long long)bx * 128 * DD;

    const int tid  = threadIdx.x;
    const int lane = tid & 31;
    const int wid  = tid >> 5;
    const int wm   = (wid & 3) * 32;
    const int wn   = (wid >> 2) * 64;

    const int r0 = tid >> 2,         c0 = tid & 3;
    const int r1 = (tid + 256) >> 2, c1 = (tid + 256) & 3;

    float acc[2][8][4];
    #pragma unroll
    for (int i = 0; i < 2; ++i)
        #pragma unroll
        for (int j = 0; j < 8; ++j)
            #pragma unroll
            for (int k = 0; k < 4; ++k) acc[i][j][k] = 0.f;

    for (int k0 = 0; k0 < DD; k0 += 32) {
        uint4 pah0 = *(const uint4*)(Ahb + (long long)r0 * DD + k0 + c0 * 8);
        uint4 pah1 = *(const uint4*)(Ahb + (long long)r1 * DD + k0 + c1 * 8);
        uint4 pal0 = *(const uint4*)(Alb + (long long)r0 * DD + k0 + c0 * 8);
        uint4 pal1 = *(const uint4*)(Alb + (long long)r1 * DD + k0 + c1 * 8);
        uint4 pbh0 = *(const uint4*)(Bhb + (long long)r0 * DD + k0 + c0 * 8);
        uint4 pbh1 = *(const uint4*)(Bhb + (long long)r1 * DD + k0 + c1 * 8);
        uint4 pbl0 = *(const uint4*)(Blb + (long long)r0 * DD + k0 + c0 * 8);
        uint4 pbl1 = *(const uint4*)(Blb + (long long)r1 * DD + k0 + c1 * 8);
        *(uint4*)(Ash + sw_off(r0, c0)) = pah0;
        *(uint4*)(Ash + sw_off(r1, c1)) = pah1;
        *(uint4*)(Asl + sw_off(r0, c0)) = pal0;
        *(uint4*)(Asl + sw_off(r1, c1)) = pal1;
        *(uint4*)(Bsh + sw_off(r0, c0)) = pbh0;
        *(uint4*)(Bsh + sw_off(r1, c1)) = pbh1;
        *(uint4*)(Bsl + sw_off(r0, c0)) = pbl0;
        *(uint4*)(Bsl + sw_off(r1, c1)) = pbl1;
        __syncthreads();

        const uint32_t ahB = smem_u32p(Ash);
        const uint32_t alB = smem_u32p(Asl);
        const uint32_t bhB = smem_u32p(Bsh);
        const uint32_t blB = smem_u32p(Bsl);

        #pragma unroll
        for (int tk = 0; tk < 2; ++tk) {
            uint32_t ah[2][4], al[2][4];
            #pragma unroll
            for (int tm = 0; tm < 2; ++tm) {
                int r = wm + tm * 16 + (lane & 7) + ((lane >> 3) & 1) * 8;
                int c = tk * 2 + (lane >> 4);
                ldsm_x4(ah[tm][0], ah[tm][1], ah[tm][2], ah[tm][3], ahB + sw_off(r, c));
                ldsm_x4(al[tm][0], al[tm][1], al[tm][2], al[tm][3], alB + sw_off(r, c));
            }
            #pragma unroll
            for (int tn = 0; tn < 4; ++tn) {
                uint32_t bh[4], bl[4];
                int r = wn + tn * 16 + (lane & 7) + ((lane >> 4) & 1) * 8;
                int c = tk * 2 + ((lane >> 3) & 1);
                ldsm_x4(bh[0], bh[1], bh[2], bh[3], bhB + sw_off(r, c));
                ldsm_x4(bl[0], bl[1], bl[2], bl[3], blB + sw_off(r, c));
                #pragma unroll
                for (int tm = 0; tm < 2; ++tm) {
                    mma_bf16(acc[tm][tn * 2 + 0], ah[tm], bh[0], bh[1]);
                    mma_bf16(acc[tm][tn * 2 + 1], ah[tm], bh[2], bh[3]);
                    mma_bf16(acc[tm][tn * 2 + 0], ah[tm], bl[0], bl[1]);
                    mma_bf16(acc[tm][tn * 2 + 1], ah[tm], bl[2], bl[3]);
                    mma_bf16(acc[tm][tn * 2 + 0], al[tm], bh[0], bh[1]);
                    mma_bf16(acc[tm][tn * 2 + 1], al[tm], bh[2], bh[3]);
                }
            }
        }
        __syncthreads();
    }

    #pragma unroll
    for (int tm = 0; tm < 2; ++tm) {
        #pragma unroll
        for (int t8 = 0; t8 < 8; ++t8) {
            int m = by * 128 + wm + tm * 16 + (lane >> 2);
            int n = bx * 128 + wn + t8 * 8 + (lane & 3) * 2;
            float2 bb = *(const float2*)(bias + n);
            float2 lo = make_float2(acc[tm][t8][0] + bb.x, acc[tm][t8][1] + bb.y);
            float2 hi = make_float2(acc[tm][t8][2] + bb.x, acc[tm][t8][3] + bb.y);
            *(float2*)(C + (long long)m * DD + n)       = lo;
            *(float2*)(C + (long long)(m + 8) * DD + n) = hi;
        }
    }
}

// ---------------------------------------------------------------------------
// top-k: histogram-threshold candidate pool (superset of approx top-48)
// -> exact fp64 rescore -> exact fp64 top-32 by parallel rank (tie: lower idx)
// -> softmax -> sparse AV. One CTA (256 thr) per query row.
// ---------------------------------------------------------------------------
#define NEG_HUGE_D (-1e300)
#define SCALE_D (0.03125)

__device__ __forceinline__ uint32_t mono_key(float s) {
    uint32_t u = __float_as_uint(s);
    return (u & 0x80000000u) ? ~u : (u | 0x80000000u);
}

__global__ __launch_bounds__(256)
void topk_softmax_av(const float* __restrict__ scores,
                     const float* __restrict__ Q,
                     const float* __restrict__ Km,
                     const float* __restrict__ V,
                     float* __restrict__ ctx)
{
    const int r = blockIdx.x;
    const int b = r >> 11;
    const int tid  = threadIdx.x;
    const int lane = tid & 31;
    const int wid  = tid >> 5;

    __shared__ float  sc[SS];            // 16 KB
    __shared__ float  qrow[DD];          // 4 KB
    __shared__ int    hist[256];
    __shared__ int    sBin1, sAbove1, sThresh16, sPCount;
    __shared__ int    pooli[MAXPOOL];
    __shared__ double cval[MAXPOOL];
    __shared__ float  selv[TOPK];
    __shared__ int    seli[TOPK];
    __shared__ float  prob[TOPK];

    const float* srow = scores + (long long)r * SS;
    for (int j = tid; j < SS; j += 256) sc[j] = srow[j];
    const float* qsrc = Q + (long long)r * DD;
    for (int j = tid; j < DD; j += 256) qrow[j] = qsrc[j];
    hist[tid] = 0;
    if (tid == 0) sPCount = 0;
    __syncthreads();

    // ---- Phase 1a: coarse histogram on key[31:24] ----
    const int base = tid * 16;
    uint32_t keys[16];
    #pragma unroll
    for (int j = 0; j < 16; ++j) {
        keys[j] = mono_key(sc[base + j]);
        atomicAdd(&hist[keys[j] >> 24], 1);
    }
    __syncthreads();

    if (tid == 0) {
        int acc = 0; int bbin = 255;
        for (; bbin >= 0; --bbin) {
            acc += hist[bbin];
            if (acc >= NCAND) break;
        }
        sBin1 = bbin;
        sAbove1 = acc - hist[bbin];   // count strictly above bin1
    }
    __syncthreads();
    const int bin1 = sBin1;
    const int above1 = sAbove1;
    hist[tid] = 0;
    __syncthreads();

    // ---- Phase 1b: refine within bin1 on key[23:16] ----
    #pragma unroll
    for (int j = 0; j < 16; ++j) {
        if ((int)(keys[j] >> 24) == bin1)
            atomicAdd(&hist[(keys[j] >> 16) & 0xFF], 1);
    }
    __syncthreads();

    if (tid == 0) {
        int acc = above1; int bbin = 255;
        for (; bbin >= 0; --bbin) {
            acc += hist[bbin];
            if (acc >= NCAND) break;
        }
        sThresh16 = (bin1 << 8) | bbin;   // pool: key>>16 >= thresh16
    }
    __syncthreads();
    const uint32_t thresh16 = (uint32_t)sThresh16;

    // ---- Phase 1c: collect pool indices (order-independent result) ----
    #pragma unroll
    for (int j = 0; j < 16; ++j) {
        if ((keys[j] >> 16) >= thresh16) {
            int pos = atomicAdd(&sPCount, 1);
            if (pos < MAXPOOL) pooli[pos] = base + j;
        }
    }
    __syncthreads();
    const int pc = min(sPCount, MAXPOOL);   // >= NCAND by construction

    // ---- Phase 2: exact fp64 rescore of pool (warp-per-candidate) ----
    const float* Kb = Km + (long long)b * SS * DD;
    for (int c = wid; c < pc; c += 8) {
        const int mi = pooli[c];
        const float* krow = Kb + (long long)mi * DD;
        double s = 0.0;
        #pragma unroll 8
        for (int i = 0; i < 32; ++i) {
            int d = lane + 32 * i;
            s += (double)qrow[d] * (double)krow[d];
        }
        #pragma unroll
        for (int off = 16; off > 0; off >>= 1)
            s += __shfl_xor_sync(0xffffffffu, s, off);
        if (lane == 0) cval[c] = s;
    }
    __syncthreads();

    // ---- Phase 3: exact fp64 top-32 by parallel rank (tie -> lower idx) ----
    if (tid < pc) {
        double v = cval[tid]; int ix = pooli[tid];
        int rank = 0;
        for (int j = 0; j < pc; ++j) {
            double vj = cval[j]; int ij = pooli[j];
            if (vj > v || (vj == v && ij < ix)) ++rank;
        }
        if (rank < TOPK) {
            selv[rank] = (float)(v * SCALE_D);
            seli[rank] = ix;
        }
    }
    __syncthreads();

    // ---- Phase 4: softmax over selected 32 (selv[0] is the max) ----
    if (tid < 32) {
        float e = expf(selv[tid] - selv[0]);
        float s = e;
        #pragma unroll
        for (int off = 16; off > 0; off >>= 1)
            s += __shfl_xor_sync(0xffffffffu, s, off);
        prob[tid] = e / s;
    }
    __syncthreads();

    // ---- Phase 5: ctx[r,:] = sum_i prob[i] * V[b, seli[i], :] ----
    const float* Vb = V + (long long)b * SS * DD;
    const int d = tid * 4;
    float4 accv = make_float4(0.f, 0.f, 0.f, 0.f);
    #pragma unroll 4
    for (int i = 0; i < TOPK; ++i) {
        const float p = prob[i];
        float4 v = *(const float4*)(Vb + (long long)seli[i] * DD + d);
        accv.x = fmaf(p, v.x, accv.x);
        accv.y = fmaf(p, v.y, accv.y);
        accv.z = fmaf(p, v.z, accv.z);
        accv.w = fmaf(p, v.w, accv.w);
    }
    *(float4*)(ctx + (long long)r * DD + d) = accv;
}

// ---------------------------------------------------------------------------
// Launch
// ---------------------------------------------------------------------------
extern "C" void kernel_launch(void* const* d_in, const int* in_sizes, int n_in,
                              void* d_out, int out_size)
{
    const float* query = (const float*)d_in[0];
    const float* mem   = (const float*)d_in[1];
    const float* Wq = (const float*)d_in[3];
    const float* bq = (const float*)d_in[4];
    const float* Wk = (const float*)d_in[5];
    const float* bk = (const float*)d_in[6];
    const float* Wv = (const float*)d_in[7];
    const float* bv = (const float*)d_in[8];
    const float* Wo = (const float*)d_in[9];
    const float* bo = (const float*)d_in[10];
    float* out = (float*)d_out;

    float *Q, *K, *V, *S, *CTX;
    __nv_bfloat16 *Qh, *Kh, *Mh, *Ml, *Ch, *Cl, *Wh, *Wl;
    cudaGetSymbolAddress((void**)&Q,   g_Q);
    cudaGetSymbolAddress((void**)&K,   g_K);
    cudaGetSymbolAddress((void**)&V,   g_V);
    cudaGetSymbolAddress((void**)&S,   g_S);
    cudaGetSymbolAddress((void**)&CTX, g_CTX);
    cudaGetSymbolAddress((void**)&Qh,  g_Qh);
    cudaGetSymbolAddress((void**)&Kh,  g_Kh);
    cudaGetSymbolAddress((void**)&Mh,  g_Mh);
    cudaGetSymbolAddress((void**)&Ml,  g_Ml);
    cudaGetSymbolAddress((void**)&Ch,  g_Ch);
    cudaGetSymbolAddress((void**)&Cl,  g_Cl);
    cudaGetSymbolAddress((void**)&Wh,  g_Wh);
    cudaGetSymbolAddress((void**)&Wl,  g_Wl);

    const float inv_sqrt_d = 1.0f / 32.0f;

    // Q/K projections (fp32, FROZEN) with fused bf16 epilogue
    gemm_nt<<<dim3(DD / BN, MQ  / BM, 1), 256>>>(query, Wq, Q, Qh, bq, MQ,  DD, DD, 1.f, 0, 0, 0);
    gemm_nt<<<dim3(DD / BN, MKV / BM, 1), 256>>>(mem,   Wk, K, Kh, bk, MKV, DD, DD, 1.f, 0, 0, 0);

    // V projection via split-bf16 tensor cores (values only)
    f32_split_bf16_kernel<<<(MKV * DD / 4 + 255) / 256, 256>>>(mem, Mh, Ml, MKV * DD / 4);
    f32_split_bf16_kernel<<<(DD  * DD / 4 + 255) / 256, 256>>>(Wv,  Wh, Wl, DD  * DD / 4);
    gemm_nt_bf16_split<<<dim3(DD / 128, MKV / 128), 256>>>(Mh, Ml, Wh, Wl, V, bv);

    // Scores (candidate nomination): plain bf16 tensor cores
    gemm_nt_bf16_scores<<<dim3(SS / 128, TQ / 128, BATCH), 256>>>(Qh, Kh, S, inv_sqrt_d);

    // Histogram pool -> exact fp64 rescore -> top-32 -> softmax -> sparse AV
    topk_softmax_av<<<MQ, 256>>>(S, Q, K, V, CTX);

    // O projection via split-bf16 tensor cores (reuse weight split buffers)
    f32_split_bf16_kernel<<<(MQ * DD / 4 + 255) / 256, 256>>>(CTX, Ch, Cl, MQ * DD / 4);
    f32_split_bf16_kernel<<<(DD * DD / 4 + 255) / 256, 256>>>(Wo,  Wh, Wl, DD * DD / 4);
    gemm_nt_bf16_split<<<dim3(DD / 128, MQ / 128), 256>>>(Ch, Cl, Wh, Wl, out, bo);
}